// round 8
// baseline (speedup 1.0000x reference)
#include <cuda_runtime.h>
#include <cuda_bf16.h>
#include <cuda_fp16.h>
#include <mma.h>
#include <cstdint>

using namespace nvcuda;
typedef __nv_bfloat16 bf16;

#define BATCH 4
#define SEQ   4096
#define DIM   512
#define ROWS  16384
#define ATTN_SCALE 0.125f
#define LN_EPS 1e-5f

/* ---------------- scratch (no allocations allowed) ---------------- */
__device__ __align__(256) float g_q [(size_t)ROWS * DIM];
__device__ __align__(256) float g_kv[(size_t)ROWS * 2 * DIM];
__device__ __align__(256) float g_S [(size_t)BATCH * SEQ * SEQ];

__device__ __align__(256) bf16 g_xh [(size_t)ROWS * DIM];
__device__ __align__(256) bf16 g_xl [(size_t)ROWS * DIM];
__device__ __align__(256) bf16 g_ch [(size_t)ROWS * DIM];
__device__ __align__(256) bf16 g_cl [(size_t)ROWS * DIM];
__device__ __align__(256) bf16 g_wqth [DIM * DIM];
__device__ __align__(256) bf16 g_wqtl [DIM * DIM];
__device__ __align__(256) bf16 g_wkvth[2 * DIM * DIM];
__device__ __align__(256) bf16 g_wkvtl[2 * DIM * DIM];
__device__ __align__(256) bf16 g_woth [DIM * DIM];
__device__ __align__(256) bf16 g_wotl [DIM * DIM];
__device__ __align__(256) bf16 g_oh [(size_t)ROWS * DIM];
__device__ __align__(256) bf16 g_ol [(size_t)ROWS * DIM];

__device__ __align__(256) __half g_qh [(size_t)ROWS * DIM];
__device__ __align__(256) __half g_ql [(size_t)ROWS * DIM];
__device__ __align__(256) __half g_kh [(size_t)ROWS * DIM];          /* single */
__device__ __align__(256) __half g_vt [(size_t)BATCH * DIM * SEQ];   /* v^T, single */
__device__ __align__(256) __half g_ph [(size_t)BATCH * SEQ * SEQ];
__device__ __align__(256) __half g_pl [(size_t)BATCH * SEQ * SEQ];

/* ---------------- cp.async helpers ---------------- */
__device__ __forceinline__ unsigned smem_u32(const void* p) {
    return (unsigned)__cvta_generic_to_shared(p);
}
#define CPA16(dst, src) \
    asm volatile("cp.async.cg.shared.global [%0], [%1], 16;\n" :: "r"(dst), "l"(src))
#define CPCOMMIT() asm volatile("cp.async.commit_group;\n" ::)
template<int N> __device__ __forceinline__ void cpwait() {
    asm volatile("cp.async.wait_group %0;\n" :: "n"(N));
}

/* ---------------- hi/lo GEMM, wide warp tiles ----------------
 * C[M,N] = alpha * (Ah+Al)[M,K] @ B^T, B given [N,K] row-major.
 * THREE: B = Bh+Bl (3 passes). !THREE: B single (2 passes).
 * Block tile 128x256, 8 warps of 64x64 (acc[4][4]), 2-stage cp.async.
 */
#define BM 128
#define BN 256
#define NT  256

template<typename T, int BKT, int RWS>
__device__ __forceinline__ void stage_tile(unsigned sm, const T* g, int ld, int tid) {
    constexpr int CPR = BKT / 8;
    constexpr int AST = BKT + 8;
    #pragma unroll
    for (int i = 0; i < (RWS * CPR) / NT; i++) {
        int idx = i * NT + tid;
        int r = idx / CPR, c = (idx % CPR) * 8;
        CPA16(sm + (unsigned)(r * AST + c) * 2, g + (size_t)r * ld + c);
    }
}

template<typename T, int BKT, bool THREE, bool SPLIT, bool BIAS>
__global__ __launch_bounds__(NT, 1) void gemm_hilo(
    const T* __restrict__ Ah, const T* __restrict__ Al,
    const T* __restrict__ Bh, const T* __restrict__ Bl,
    float* __restrict__ C, bf16* __restrict__ Ch, bf16* __restrict__ Cl,
    const float* __restrict__ bias,
    int K, int lda, int ldb, int ldc,
    long long sA, long long sB, long long sC, float alpha)
{
    extern __shared__ char smem[];
    constexpr int AST = BKT + 8;
    constexpr unsigned TA = 128u * AST * 2u;          /* A tile bytes   */
    constexpr unsigned TB = 256u * AST * 2u;          /* B tile bytes   */
    constexpr unsigned STG = 2u * TA + (THREE ? 2u : 1u) * TB;

    const int tid  = threadIdx.x;
    const int warp = tid >> 5;
    const int wm = warp >> 2;      /* 0..1 : 64-row slab  */
    const int wn = warp & 3;       /* 0..3 : 64-col slab  */
    const int m0 = blockIdx.y * BM;
    const int n0 = blockIdx.x * BN;
    const long long zb = blockIdx.z;
    const unsigned sb0 = smem_u32(smem);

    const T* gAh = Ah + zb * sA + (size_t)m0 * lda;
    const T* gAl = Al + zb * sA + (size_t)m0 * lda;
    const T* gBh = Bh + zb * sB + (size_t)n0 * ldb;
    const T* gBl = THREE ? (Bl + zb * sB + (size_t)n0 * ldb) : nullptr;

    wmma::fragment<wmma::accumulator, 16, 16, 16, float> acc[4][4];
    #pragma unroll
    for (int i = 0; i < 4; i++)
        #pragma unroll
        for (int j = 0; j < 4; j++)
            wmma::fill_fragment(acc[i][j], 0.0f);

    auto stage = [&](int s, int k0) {
        unsigned sp = sb0 + (unsigned)s * STG;
        stage_tile<T, BKT, 128>(sp,           gAh + k0, lda, tid);
        stage_tile<T, BKT, 128>(sp + TA,      gAl + k0, lda, tid);
        stage_tile<T, BKT, 256>(sp + 2u * TA, gBh + k0, ldb, tid);
        if (THREE) stage_tile<T, BKT, 256>(sp + 2u * TA + TB, gBl + k0, ldb, tid);
        CPCOMMIT();
    };

    stage(0, 0);
    int s = 0;
    for (int k0 = 0; k0 < K; k0 += BKT) {
        if (k0 + BKT < K) { stage(s ^ 1, k0 + BKT); cpwait<1>(); }
        else              { cpwait<0>(); }
        __syncthreads();

        T* sAh = (T*)(smem + s * STG);
        T* sAl = (T*)(smem + s * STG + TA);
        T* sBh = (T*)(smem + s * STG + 2 * TA);
        T* sBl = (T*)(smem + s * STG + 2 * TA + TB);

        #pragma unroll
        for (int kk = 0; kk < BKT; kk += 16) {
            wmma::fragment<wmma::matrix_a, 16, 16, 16, T, wmma::row_major> a[4];
            wmma::fragment<wmma::matrix_b, 16, 16, 16, T, wmma::col_major> b[4];
            #pragma unroll
            for (int i = 0; i < 4; i++)
                wmma::load_matrix_sync(a[i], sAh + (wm * 64 + i * 16) * AST + kk, AST);
            #pragma unroll
            for (int j = 0; j < 4; j++)
                wmma::load_matrix_sync(b[j], sBh + (wn * 64 + j * 16) * AST + kk, AST);

            /* pass 1: Ah x Bh */
            #pragma unroll
            for (int i = 0; i < 4; i++)
                #pragma unroll
                for (int j = 0; j < 4; j++)
                    wmma::mma_sync(acc[i][j], a[i], b[j], acc[i][j]);

            if (THREE) {
                /* pass 2: Ah x Bl (reuse b regs) */
                wmma::fragment<wmma::matrix_b, 16, 16, 16, T, wmma::col_major> bl[4];
                #pragma unroll
                for (int j = 0; j < 4; j++)
                    wmma::load_matrix_sync(bl[j], sBl + (wn * 64 + j * 16) * AST + kk, AST);
                #pragma unroll
                for (int i = 0; i < 4; i++)
                    #pragma unroll
                    for (int j = 0; j < 4; j++)
                        wmma::mma_sync(acc[i][j], a[i], bl[j], acc[i][j]);
            }

            /* pass 3 (or 2): Al x Bh */
            #pragma unroll
            for (int i = 0; i < 4; i++)
                wmma::load_matrix_sync(a[i], sAl + (wm * 64 + i * 16) * AST + kk, AST);
            #pragma unroll
            for (int i = 0; i < 4; i++)
                #pragma unroll
                for (int j = 0; j < 4; j++)
                    wmma::mma_sync(acc[i][j], a[i], b[j], acc[i][j]);
        }
        __syncthreads();
        s ^= 1;
    }

    /* ---- epilogue: 64-row halves through smem (64 x 264 fp32) ---- */
    #pragma unroll
    for (int i = 0; i < 4; i++)
        #pragma unroll
        for (int j = 0; j < 4; j++)
            #pragma unroll
            for (int t = 0; t < acc[i][j].num_elements; t++)
                acc[i][j].x[t] *= alpha;

    float* cs = (float*)smem;
    #pragma unroll
    for (int half = 0; half < 2; half++) {
        if (wm == half) {
            #pragma unroll
            for (int i = 0; i < 4; i++)
                #pragma unroll
                for (int j = 0; j < 4; j++)
                    wmma::store_matrix_sync(cs + (i * 16) * 264 + wn * 64 + j * 16,
                                            acc[i][j], 264, wmma::mem_row_major);
        }
        __syncthreads();

        #pragma unroll
        for (int it = 0; it < 16; it++) {
            int idx = it * NT + tid;          /* 0..4095 float4 slots: 64 x 64 */
            int r = idx >> 6, c4 = (idx & 63) * 4;
            float4 v = *(float4*)(cs + r * 264 + c4);
            if (BIAS) {
                v.x += bias[n0 + c4 + 0];
                v.y += bias[n0 + c4 + 1];
                v.z += bias[n0 + c4 + 2];
                v.w += bias[n0 + c4 + 3];
            }
            size_t base = (size_t)zb * sC + (size_t)(m0 + half * 64 + r) * ldc + n0 + c4;
            if (SPLIT) {
                bf16 h0 = __float2bfloat16(v.x), h1 = __float2bfloat16(v.y);
                bf16 h2 = __float2bfloat16(v.z), h3 = __float2bfloat16(v.w);
                __nv_bfloat162 t;
                t.x = h0; t.y = h1; *(__nv_bfloat162*)(Ch + base) = t;
                t.x = h2; t.y = h3; *(__nv_bfloat162*)(Ch + base + 2) = t;
                t.x = __float2bfloat16(v.x - __bfloat162float(h0));
                t.y = __float2bfloat16(v.y - __bfloat162float(h1));
                *(__nv_bfloat162*)(Cl + base) = t;
                t.x = __float2bfloat16(v.z - __bfloat162float(h2));
                t.y = __float2bfloat16(v.w - __bfloat162float(h3));
                *(__nv_bfloat162*)(Cl + base + 2) = t;
            } else {
                *(float4*)(C + base) = v;
            }
        }
        __syncthreads();
    }
}

/* ---------------- fused input split: x -> xh/xl, ctx -> ch/cl ------------- */
__global__ __launch_bounds__(256) void split_inputs(
    const float* __restrict__ x, const float* __restrict__ ctx,
    bf16* __restrict__ xh, bf16* __restrict__ xl,
    bf16* __restrict__ ch, bf16* __restrict__ cl)
{
    const float* in = blockIdx.y ? ctx : x;
    bf16* h = blockIdx.y ? ch : xh;
    bf16* l = blockIdx.y ? cl : xl;
    size_t i = (size_t)blockIdx.x * 256 + threadIdx.x;
    float4 v = ((const float4*)in)[i];
    bf16 h0 = __float2bfloat16(v.x), h1 = __float2bfloat16(v.y);
    bf16 h2 = __float2bfloat16(v.z), h3 = __float2bfloat16(v.w);
    __nv_bfloat162 t;
    t.x = h0; t.y = h1; *(__nv_bfloat162*)(h + i * 4) = t;
    t.x = h2; t.y = h3; *(__nv_bfloat162*)(h + i * 4 + 2) = t;
    t.x = __float2bfloat16(v.x - __bfloat162float(h0));
    t.y = __float2bfloat16(v.y - __bfloat162float(h1));
    *(__nv_bfloat162*)(l + i * 4) = t;
    t.x = __float2bfloat16(v.z - __bfloat162float(h2));
    t.y = __float2bfloat16(v.w - __bfloat162float(h3));
    *(__nv_bfloat162*)(l + i * 4 + 2) = t;
}

/* ---------------- all weights: W[K,N] -> W^T[N,K] bf16 hi/lo ------------- */
__global__ __launch_bounds__(256) void wsplit_all(
    const float* __restrict__ Wq, const float* __restrict__ Wkv, const float* __restrict__ Wo,
    bf16* __restrict__ qth, bf16* __restrict__ qtl,
    bf16* __restrict__ kvth, bf16* __restrict__ kvtl,
    bf16* __restrict__ oth, bf16* __restrict__ otl)
{
    __shared__ float t[32][33];
    int bx = blockIdx.x;
    const float* W; bf16 *th, *tl; int N, tidx;
    if (bx < 256)      { W = Wq;  th = qth;  tl = qtl;  N = DIM;     tidx = bx; }
    else if (bx < 768) { W = Wkv; th = kvth; tl = kvtl; N = 2 * DIM; tidx = bx - 256; }
    else               { W = Wo;  th = oth;  tl = otl;  N = DIM;     tidx = bx - 768; }
    int nT = N / 32;
    int n0 = (tidx % nT) * 32, k0 = (tidx / nT) * 32;
    int tx = threadIdx.x & 31, ty = threadIdx.x >> 5;
    #pragma unroll
    for (int j = 0; j < 4; j++) {
        int r = ty + j * 8;
        t[r][tx] = W[(size_t)(k0 + r) * N + n0 + tx];
    }
    __syncthreads();
    #pragma unroll
    for (int j = 0; j < 4; j++) {
        int r = ty + j * 8;
        float v = t[tx][r];
        size_t o = (size_t)(n0 + r) * DIM + k0 + tx;
        bf16 h = __float2bfloat16(v);
        th[o] = h;
        tl[o] = __float2bfloat16(v - __bfloat162float(h));
    }
}

/* ---------------- fused attention prep ---------------- */
__global__ __launch_bounds__(256) void prep_attn(
    const float* __restrict__ q, const float* __restrict__ kv,
    const float* __restrict__ g, const float* __restrict__ b,
    __half* __restrict__ qh, __half* __restrict__ ql,
    __half* __restrict__ kh, __half* __restrict__ vt)
{
    const int mode = blockIdx.y;
    int tid = threadIdx.x;

    if (mode == 2) {                     /* v transpose, fp16 single */
        if (blockIdx.x >= 8192) return;
        __shared__ float t[32][33];
        int bx = blockIdx.x;
        int bb = bx >> 11;
        int rem = bx & 2047;
        int d0 = (rem >> 7) * 32;
        int m0 = (rem & 127) * 32;
        int tx = tid & 31, ty = tid >> 5;
        const float* src = kv + ((size_t)bb * SEQ) * (2 * DIM) + DIM;
        #pragma unroll
        for (int j = 0; j < 4; j++) {
            int r = ty + j * 8;
            t[r][tx] = src[(size_t)(m0 + r) * (2 * DIM) + d0 + tx];
        }
        __syncthreads();
        #pragma unroll
        for (int j = 0; j < 4; j++) {
            int r = ty + j * 8;
            vt[((size_t)bb * DIM + d0 + r) * SEQ + m0 + tx] = __float2half(t[tx][r]);
        }
        return;
    }

    __shared__ float red[16];
    const float* row = (mode == 0) ? q + (size_t)blockIdx.x * DIM
                                   : kv + (size_t)blockIdx.x * (2 * DIM);
    float x0 = row[tid];
    float x1 = row[tid + 256];
    float s  = x0 + x1;
    float sq = x0 * x0 + x1 * x1;
    #pragma unroll
    for (int o = 16; o > 0; o >>= 1) {
        s  += __shfl_xor_sync(0xffffffffu, s,  o);
        sq += __shfl_xor_sync(0xffffffffu, sq, o);
    }
    if ((tid & 31) == 0) { red[tid >> 5] = s; red[8 + (tid >> 5)] = sq; }
    __syncthreads();
    if (tid < 32) {
        float vs = (tid < 8) ? red[tid] : 0.0f;
        float vq = (tid < 8) ? red[8 + tid] : 0.0f;
        #pragma unroll
        for (int o = 4; o > 0; o >>= 1) {
            vs += __shfl_xor_sync(0xffffffffu, vs, o);
            vq += __shfl_xor_sync(0xffffffffu, vq, o);
        }
        if (tid == 0) { red[0] = vs; red[1] = vq; }
    }
    __syncthreads();
    float mean = red[0] * (1.0f / 512.0f);
    float var  = red[1] * (1.0f / 512.0f) - mean * mean;
    float rstd = rsqrtf(var + LN_EPS);
    float y0 = (x0 - mean) * rstd * g[tid]       + b[tid];
    float y1 = (x1 - mean) * rstd * g[tid + 256] + b[tid + 256];
    if (mode == 0) {
        __half* hr = qh + (size_t)blockIdx.x * DIM;
        __half* lr = ql + (size_t)blockIdx.x * DIM;
        __half h0 = __float2half(y0);
        __half h1 = __float2half(y1);
        hr[tid]       = h0;
        hr[tid + 256] = h1;
        lr[tid]       = __float2half(y0 - __half2float(h0));
        lr[tid + 256] = __float2half(y1 - __half2float(h1));
    } else {
        __half* hr = kh + (size_t)blockIdx.x * DIM;
        hr[tid]       = __float2half(y0);
        hr[tid + 256] = __float2half(y1);
    }
}

/* ---------------- softmax(4096) fp32 -> fp16 hi/lo ---------------- */
__global__ __launch_bounds__(256) void softmax_split(
    const float* __restrict__ S, __half* __restrict__ ph, __half* __restrict__ pl)
{
    __shared__ float red[8];
    const float* row = S + (size_t)blockIdx.x * SEQ;
    __half* hr = ph + (size_t)blockIdx.x * SEQ;
    __half* lr = pl + (size_t)blockIdx.x * SEQ;
    int tid = threadIdx.x;
    float v[16];
    float mx = -1e30f;
    #pragma unroll
    for (int i = 0; i < 16; i++) { v[i] = row[tid + i * 256]; mx = fmaxf(mx, v[i]); }
    #pragma unroll
    for (int o = 16; o > 0; o >>= 1) mx = fmaxf(mx, __shfl_xor_sync(0xffffffffu, mx, o));
    if ((tid & 31) == 0) red[tid >> 5] = mx;
    __syncthreads();
    if (tid < 32) {
        float m = (tid < 8) ? red[tid] : -1e30f;
        #pragma unroll
        for (int o = 4; o > 0; o >>= 1) m = fmaxf(m, __shfl_xor_sync(0xffffffffu, m, o));
        if (tid == 0) red[0] = m;
    }
    __syncthreads();
    mx = red[0];
    __syncthreads();
    float s = 0.0f;
    #pragma unroll
    for (int i = 0; i < 16; i++) { v[i] = __expf(v[i] - mx); s += v[i]; }
    #pragma unroll
    for (int o = 16; o > 0; o >>= 1) s += __shfl_xor_sync(0xffffffffu, s, o);
    if ((tid & 31) == 0) red[tid >> 5] = s;
    __syncthreads();
    if (tid < 32) {
        float m = (tid < 8) ? red[tid] : 0.0f;
        #pragma unroll
        for (int o = 4; o > 0; o >>= 1) m += __shfl_xor_sync(0xffffffffu, m, o);
        if (tid == 0) red[0] = m;
    }
    __syncthreads();
    float inv = 1.0f / red[0];
    #pragma unroll
    for (int i = 0; i < 16; i++) {
        float p = v[i] * inv;
        __half h = __float2half(p);
        hr[tid + i * 256] = h;
        lr[tid + i * 256] = __float2half(p - __half2float(h));
    }
}

/* ---------------- launcher ---------------- */
#define SMEM_P 122880u     /* proj: 2 stages x (2A + 2B) tiles, BK=32   */
#define SMEM_A 147456u     /* attn: 2 stages x (2A + 1B) tiles, BK=64   */

extern "C" void kernel_launch(void* const* d_in, const int* in_sizes, int n_in,
                              void* d_out, int out_size)
{
    const float* x    = (const float*)d_in[0];
    const float* ctx  = (const float*)d_in[1];
    const float* Wq   = (const float*)d_in[2];
    const float* Wkv  = (const float*)d_in[3];
    const float* Wo   = (const float*)d_in[4];
    const float* bo   = (const float*)d_in[5];
    const float* ln_g = (const float*)d_in[6];
    const float* ln_b = (const float*)d_in[7];
    float* out = (float*)d_out;

    float *q, *kv, *S;
    bf16 *xh, *xl, *ch, *cl, *wqth, *wqtl, *wkvth, *wkvtl, *woth, *wotl, *oh, *ol;
    __half *qh, *ql, *kh, *vt, *ph, *pl;
    cudaGetSymbolAddress((void**)&q,    g_q);
    cudaGetSymbolAddress((void**)&kv,   g_kv);
    cudaGetSymbolAddress((void**)&S,    g_S);
    cudaGetSymbolAddress((void**)&xh,   g_xh);    cudaGetSymbolAddress((void**)&xl,   g_xl);
    cudaGetSymbolAddress((void**)&ch,   g_ch);    cudaGetSymbolAddress((void**)&cl,   g_cl);
    cudaGetSymbolAddress((void**)&wqth, g_wqth);  cudaGetSymbolAddress((void**)&wqtl, g_wqtl);
    cudaGetSymbolAddress((void**)&wkvth,g_wkvth); cudaGetSymbolAddress((void**)&wkvtl,g_wkvtl);
    cudaGetSymbolAddress((void**)&woth, g_woth);  cudaGetSymbolAddress((void**)&wotl, g_wotl);
    cudaGetSymbolAddress((void**)&oh,   g_oh);    cudaGetSymbolAddress((void**)&ol,   g_ol);
    cudaGetSymbolAddress((void**)&qh,   g_qh);    cudaGetSymbolAddress((void**)&ql,   g_ql);
    cudaGetSymbolAddress((void**)&kh,   g_kh);    cudaGetSymbolAddress((void**)&vt,   g_vt);
    cudaGetSymbolAddress((void**)&ph,   g_ph);    cudaGetSymbolAddress((void**)&pl,   g_pl);

    cudaFuncSetAttribute(gemm_hilo<bf16,  32, true,  false, false>,
                         cudaFuncAttributeMaxDynamicSharedMemorySize, SMEM_P);
    cudaFuncSetAttribute(gemm_hilo<bf16,  32, true,  false, true>,
                         cudaFuncAttributeMaxDynamicSharedMemorySize, SMEM_P);
    cudaFuncSetAttribute(gemm_hilo<__half,64, false, false, false>,
                         cudaFuncAttributeMaxDynamicSharedMemorySize, SMEM_A);
    cudaFuncSetAttribute(gemm_hilo<__half,64, false, true,  false>,
                         cudaFuncAttributeMaxDynamicSharedMemorySize, SMEM_A);

    /* 0: split inputs */
    split_inputs<<<dim3(ROWS * DIM / 4 / 256, 2), 256>>>(x, ctx, xh, xl, ch, cl);
    /* 1: split+transpose all weights */
    wsplit_all<<<1024, 256>>>(Wq, Wkv, Wo, wqth, wqtl, wkvth, wkvtl, woth, wotl);

    /* 2: q = x @ Wq (bf16x3, BK=32) */
    gemm_hilo<bf16,32,true,false,false><<<dim3(DIM / BN, ROWS / BM, 1), NT, SMEM_P>>>(
        xh, xl, wqth, wqtl, q, nullptr, nullptr, nullptr,
        DIM, DIM, DIM, DIM, 0, 0, 0, 1.0f);

    /* 3: kv = ctx @ Wkv (bf16x3, BK=32) */
    gemm_hilo<bf16,32,true,false,false><<<dim3(2 * DIM / BN, ROWS / BM, 1), NT, SMEM_P>>>(
        ch, cl, wkvth, wkvtl, kv, nullptr, nullptr, nullptr,
        DIM, DIM, DIM, 2 * DIM, 0, 0, 0, 1.0f);

    /* 4: LN(q)->fp16 hi/lo, LN(k)->fp16, v->v^T fp16 */
    prep_attn<<<dim3(ROWS, 3), 256>>>(q, kv, ln_g, ln_b, qh, ql, kh, vt);

    /* 5: S = scale * q @ k^T (fp16 x2, BK=64) */
    gemm_hilo<__half,64,false,false,false><<<dim3(SEQ / BN, SEQ / BM, BATCH), NT, SMEM_A>>>(
        qh, ql, kh, nullptr, S, nullptr, nullptr, nullptr,
        DIM, DIM, DIM, SEQ,
        (long long)SEQ * DIM, (long long)SEQ * DIM, (long long)SEQ * SEQ, ATTN_SCALE);

    /* 6: P = softmax(S) -> fp16 hi/lo */
    softmax_split<<<BATCH * SEQ, 256>>>(S, ph, pl);

    /* 7: O = P @ v (fp16 x2, BK=64, split bf16 out) */
    gemm_hilo<__half,64,false,true,false><<<dim3(DIM / BN, SEQ / BM, BATCH), NT, SMEM_A>>>(
        ph, pl, vt, nullptr, nullptr, oh, ol, nullptr,
        SEQ, SEQ, SEQ, DIM,
        (long long)SEQ * SEQ, (long long)DIM * SEQ, (long long)SEQ * DIM, 1.0f);

    /* 8: out = O @ Wo + bo (bf16x3, BK=32) */
    gemm_hilo<bf16,32,true,false,true><<<dim3(DIM / BN, ROWS / BM, 1), NT, SMEM_P>>>(
        oh, ol, woth, wotl, out, nullptr, nullptr, bo,
        DIM, DIM, DIM, DIM, 0, 0, 0, 1.0f);
}

// round 9
// speedup vs baseline: 1.3907x; 1.3907x over previous
#include <cuda_runtime.h>
#include <cuda_bf16.h>
#include <cuda_fp16.h>
#include <mma.h>
#include <cstdint>

using namespace nvcuda;
typedef __nv_bfloat16 bf16;

#define BATCH 4
#define SEQ   4096
#define DIM   512
#define ROWS  16384
#define ATTN_SCALE 0.125f
#define LN_EPS 1e-5f

/* ---------------- scratch (no allocations allowed) ---------------- */
__device__ __align__(256) float g_q [(size_t)ROWS * DIM];
__device__ __align__(256) float g_kv[(size_t)ROWS * 2 * DIM];
__device__ __align__(256) float g_S [(size_t)BATCH * SEQ * SEQ];

__device__ __align__(256) bf16 g_xh [(size_t)ROWS * DIM];
__device__ __align__(256) bf16 g_xl [(size_t)ROWS * DIM];
__device__ __align__(256) bf16 g_ch [(size_t)ROWS * DIM];
__device__ __align__(256) bf16 g_cl [(size_t)ROWS * DIM];
__device__ __align__(256) bf16 g_wqth [DIM * DIM];
__device__ __align__(256) bf16 g_wqtl [DIM * DIM];
__device__ __align__(256) bf16 g_wkvth[2 * DIM * DIM];
__device__ __align__(256) bf16 g_wkvtl[2 * DIM * DIM];
__device__ __align__(256) bf16 g_woth [DIM * DIM];
__device__ __align__(256) bf16 g_wotl [DIM * DIM];
__device__ __align__(256) bf16 g_oh [(size_t)ROWS * DIM];
__device__ __align__(256) bf16 g_ol [(size_t)ROWS * DIM];

__device__ __align__(256) __half g_qh [(size_t)ROWS * DIM];          /* single */
__device__ __align__(256) __half g_kh [(size_t)ROWS * DIM];          /* single */
__device__ __align__(256) __half g_vt [(size_t)BATCH * DIM * SEQ];   /* v^T, single */
__device__ __align__(256) __half g_ph [(size_t)BATCH * SEQ * SEQ];   /* single */

/* ---------------- cp.async helpers ---------------- */
__device__ __forceinline__ unsigned smem_u32(const void* p) {
    return (unsigned)__cvta_generic_to_shared(p);
}
#define CPA16(dst, src) \
    asm volatile("cp.async.cg.shared.global [%0], [%1], 16;\n" :: "r"(dst), "l"(src))
#define CPCOMMIT() asm volatile("cp.async.commit_group;\n" ::)
template<int N> __device__ __forceinline__ void cpwait() {
    asm volatile("cp.async.wait_group %0;\n" :: "n"(N));
}

/* ---------------- hi/lo GEMM ----------------
 * C[M,N] = alpha * A @ B^T, B given [N,K] row-major.
 * PASSES=3: (Ah+Al)(Bh+Bl) drop AlBl.  PASSES=2: (Ah+Al)Bh.  PASSES=1: Ah Bh.
 * 128x128 tiles, BKT k-chunk, 256 thr, 8 warps of 64x32, 2-stage cp.async.
 */
#define BM 128
#define BN 128
#define NT  256

template<typename T, int BKT>
__device__ __forceinline__ void stage_tile(unsigned sm, const T* g, int ld, int tid) {
    constexpr int CPR = BKT / 8;
    constexpr int AST = BKT + 8;
    #pragma unroll
    for (int i = 0; i < (128 * CPR) / NT; i++) {
        int idx = i * NT + tid;
        int r = idx / CPR, c = (idx % CPR) * 8;
        CPA16(sm + (unsigned)(r * AST + c) * 2, g + (size_t)r * ld + c);
    }
}

template<typename T, int BKT, int PASSES, bool SPLIT, bool BIAS>
__global__ __launch_bounds__(NT, 2) void gemm_hilo(
    const T* __restrict__ Ah, const T* __restrict__ Al,
    const T* __restrict__ Bh, const T* __restrict__ Bl,
    float* __restrict__ C, bf16* __restrict__ Ch, bf16* __restrict__ Cl,
    const float* __restrict__ bias,
    int K, int lda, int ldb, int ldc,
    long long sA, long long sB, long long sC, float alpha)
{
    extern __shared__ char smem[];
    constexpr int AST = BKT + 8;
    constexpr unsigned TSZ = 128u * AST * 2u;
    constexpr unsigned NTILE = (PASSES == 3) ? 4u : (PASSES == 2 ? 3u : 2u);
    constexpr unsigned STG = NTILE * TSZ;

    const int tid  = threadIdx.x;
    const int warp = tid >> 5;
    const int wm = warp >> 2;
    const int wn = warp & 3;
    const int m0 = blockIdx.y * BM;
    const int n0 = blockIdx.x * BN;
    const long long zb = blockIdx.z;
    const unsigned sb0 = smem_u32(smem);

    const T* gAh = Ah + zb * sA + (size_t)m0 * lda;
    const T* gAl = (PASSES >= 2) ? (Al + zb * sA + (size_t)m0 * lda) : nullptr;
    const T* gBh = Bh + zb * sB + (size_t)n0 * ldb;
    const T* gBl = (PASSES == 3) ? (Bl + zb * sB + (size_t)n0 * ldb) : nullptr;

    wmma::fragment<wmma::accumulator, 16, 16, 16, float> acc[4][2];
    #pragma unroll
    for (int i = 0; i < 4; i++)
        #pragma unroll
        for (int j = 0; j < 2; j++)
            wmma::fill_fragment(acc[i][j], 0.0f);

    auto stage = [&](int s, int k0) {
        unsigned sp = sb0 + (unsigned)s * STG;
        stage_tile<T, BKT>(sp, gAh + k0, lda, tid);
        stage_tile<T, BKT>(sp + (NTILE - 1u) * TSZ, gBh + k0, ldb, tid);
        if (PASSES >= 2) stage_tile<T, BKT>(sp + TSZ, gAl + k0, lda, tid);
        if (PASSES == 3) stage_tile<T, BKT>(sp + 2u * TSZ, gBl + k0, ldb, tid);
        CPCOMMIT();
    };

    stage(0, 0);
    int s = 0;
    for (int k0 = 0; k0 < K; k0 += BKT) {
        if (k0 + BKT < K) { stage(s ^ 1, k0 + BKT); cpwait<1>(); }
        else              { cpwait<0>(); }
        __syncthreads();

        T* sAh = (T*)(smem + s * STG);
        T* sAl = (T*)(smem + s * STG + TSZ);
        T* sBl = (T*)(smem + s * STG + 2 * TSZ);
        T* sBh = (T*)(smem + s * STG + (NTILE - 1u) * TSZ);

        #pragma unroll
        for (int kk = 0; kk < BKT; kk += 16) {
            wmma::fragment<wmma::matrix_a, 16, 16, 16, T, wmma::row_major> a[4];
            wmma::fragment<wmma::matrix_b, 16, 16, 16, T, wmma::col_major> bh[2];
            #pragma unroll
            for (int i = 0; i < 4; i++)
                wmma::load_matrix_sync(a[i], sAh + (wm * 64 + i * 16) * AST + kk, AST);
            #pragma unroll
            for (int j = 0; j < 2; j++)
                wmma::load_matrix_sync(bh[j], sBh + (wn * 32 + j * 16) * AST + kk, AST);

            /* pass 1: Ah x Bh */
            #pragma unroll
            for (int i = 0; i < 4; i++)
                #pragma unroll
                for (int j = 0; j < 2; j++)
                    wmma::mma_sync(acc[i][j], a[i], bh[j], acc[i][j]);

            if (PASSES == 3) {
                wmma::fragment<wmma::matrix_b, 16, 16, 16, T, wmma::col_major> bl[2];
                #pragma unroll
                for (int j = 0; j < 2; j++)
                    wmma::load_matrix_sync(bl[j], sBl + (wn * 32 + j * 16) * AST + kk, AST);
                #pragma unroll
                for (int i = 0; i < 4; i++)
                    #pragma unroll
                    for (int j = 0; j < 2; j++)
                        wmma::mma_sync(acc[i][j], a[i], bl[j], acc[i][j]);
            }

            if (PASSES >= 2) {
                #pragma unroll
                for (int i = 0; i < 4; i++)
                    wmma::load_matrix_sync(a[i], sAl + (wm * 64 + i * 16) * AST + kk, AST);
                #pragma unroll
                for (int i = 0; i < 4; i++)
                    #pragma unroll
                    for (int j = 0; j < 2; j++)
                        wmma::mma_sync(acc[i][j], a[i], bh[j], acc[i][j]);
            }
        }
        __syncthreads();
        s ^= 1;
    }

    /* ---- epilogue via smem (128 x 132 fp32) ---- */
    float* cs = (float*)smem;
    #pragma unroll
    for (int i = 0; i < 4; i++)
        #pragma unroll
        for (int j = 0; j < 2; j++) {
            #pragma unroll
            for (int t = 0; t < acc[i][j].num_elements; t++)
                acc[i][j].x[t] *= alpha;
            wmma::store_matrix_sync(cs + (wm * 64 + i * 16) * 132 + wn * 32 + j * 16,
                                    acc[i][j], 132, wmma::mem_row_major);
        }
    __syncthreads();

    #pragma unroll
    for (int it = 0; it < 16; it++) {
        int idx = it * NT + tid;
        int r = idx >> 5, c4 = (idx & 31) * 4;
        float4 v = *(float4*)(cs + r * 132 + c4);
        if (BIAS) {
            v.x += bias[n0 + c4 + 0];
            v.y += bias[n0 + c4 + 1];
            v.z += bias[n0 + c4 + 2];
            v.w += bias[n0 + c4 + 3];
        }
        size_t base = (size_t)zb * sC + (size_t)(m0 + r) * ldc + n0 + c4;
        if (SPLIT) {
            bf16 h0 = __float2bfloat16(v.x), h1 = __float2bfloat16(v.y);
            bf16 h2 = __float2bfloat16(v.z), h3 = __float2bfloat16(v.w);
            __nv_bfloat162 t;
            t.x = h0; t.y = h1; *(__nv_bfloat162*)(Ch + base) = t;
            t.x = h2; t.y = h3; *(__nv_bfloat162*)(Ch + base + 2) = t;
            t.x = __float2bfloat16(v.x - __bfloat162float(h0));
            t.y = __float2bfloat16(v.y - __bfloat162float(h1));
            *(__nv_bfloat162*)(Cl + base) = t;
            t.x = __float2bfloat16(v.z - __bfloat162float(h2));
            t.y = __float2bfloat16(v.w - __bfloat162float(h3));
            *(__nv_bfloat162*)(Cl + base + 2) = t;
        } else {
            *(float4*)(C + base) = v;
        }
    }
}

/* ---------------- fused input split: x -> xh/xl, ctx -> ch/cl ------------- */
__global__ __launch_bounds__(256) void split_inputs(
    const float* __restrict__ x, const float* __restrict__ ctx,
    bf16* __restrict__ xh, bf16* __restrict__ xl,
    bf16* __restrict__ ch, bf16* __restrict__ cl)
{
    const float* in = blockIdx.y ? ctx : x;
    bf16* h = blockIdx.y ? ch : xh;
    bf16* l = blockIdx.y ? cl : xl;
    size_t i = (size_t)blockIdx.x * 256 + threadIdx.x;
    float4 v = ((const float4*)in)[i];
    bf16 h0 = __float2bfloat16(v.x), h1 = __float2bfloat16(v.y);
    bf16 h2 = __float2bfloat16(v.z), h3 = __float2bfloat16(v.w);
    __nv_bfloat162 t;
    t.x = h0; t.y = h1; *(__nv_bfloat162*)(h + i * 4) = t;
    t.x = h2; t.y = h3; *(__nv_bfloat162*)(h + i * 4 + 2) = t;
    t.x = __float2bfloat16(v.x - __bfloat162float(h0));
    t.y = __float2bfloat16(v.y - __bfloat162float(h1));
    *(__nv_bfloat162*)(l + i * 4) = t;
    t.x = __float2bfloat16(v.z - __bfloat162float(h2));
    t.y = __float2bfloat16(v.w - __bfloat162float(h3));
    *(__nv_bfloat162*)(l + i * 4 + 2) = t;
}

/* ---------------- all weights: W[K,N] -> W^T[N,K] bf16 hi/lo ------------- */
__global__ __launch_bounds__(256) void wsplit_all(
    const float* __restrict__ Wq, const float* __restrict__ Wkv, const float* __restrict__ Wo,
    bf16* __restrict__ qth, bf16* __restrict__ qtl,
    bf16* __restrict__ kvth, bf16* __restrict__ kvtl,
    bf16* __restrict__ oth, bf16* __restrict__ otl)
{
    __shared__ float t[32][33];
    int bx = blockIdx.x;
    const float* W; bf16 *th, *tl; int N, tidx;
    if (bx < 256)      { W = Wq;  th = qth;  tl = qtl;  N = DIM;     tidx = bx; }
    else if (bx < 768) { W = Wkv; th = kvth; tl = kvtl; N = 2 * DIM; tidx = bx - 256; }
    else               { W = Wo;  th = oth;  tl = otl;  N = DIM;     tidx = bx - 768; }
    int nT = N / 32;
    int n0 = (tidx % nT) * 32, k0 = (tidx / nT) * 32;
    int tx = threadIdx.x & 31, ty = threadIdx.x >> 5;
    #pragma unroll
    for (int j = 0; j < 4; j++) {
        int r = ty + j * 8;
        t[r][tx] = W[(size_t)(k0 + r) * N + n0 + tx];
    }
    __syncthreads();
    #pragma unroll
    for (int j = 0; j < 4; j++) {
        int r = ty + j * 8;
        float v = t[tx][r];
        size_t o = (size_t)(n0 + r) * DIM + k0 + tx;
        bf16 h = __float2bfloat16(v);
        th[o] = h;
        tl[o] = __float2bfloat16(v - __bfloat162float(h));
    }
}

/* ---------------- fused attention prep: LN(q)->fp16, LN(k)->fp16,
                    v -> v^T fp16 ---------------- */
__global__ __launch_bounds__(256) void prep_attn(
    const float* __restrict__ q, const float* __restrict__ kv,
    const float* __restrict__ g, const float* __restrict__ b,
    __half* __restrict__ qh, __half* __restrict__ kh, __half* __restrict__ vt)
{
    const int mode = blockIdx.y;
    int tid = threadIdx.x;

    if (mode == 2) {                     /* v transpose, fp16 single */
        if (blockIdx.x >= 8192) return;
        __shared__ float t[32][33];
        int bx = blockIdx.x;
        int bb = bx >> 11;
        int rem = bx & 2047;
        int d0 = (rem >> 7) * 32;
        int m0 = (rem & 127) * 32;
        int tx = tid & 31, ty = tid >> 5;
        const float* src = kv + ((size_t)bb * SEQ) * (2 * DIM) + DIM;
        #pragma unroll
        for (int j = 0; j < 4; j++) {
            int r = ty + j * 8;
            t[r][tx] = src[(size_t)(m0 + r) * (2 * DIM) + d0 + tx];
        }
        __syncthreads();
        #pragma unroll
        for (int j = 0; j < 4; j++) {
            int r = ty + j * 8;
            vt[((size_t)bb * DIM + d0 + r) * SEQ + m0 + tx] = __float2half(t[tx][r]);
        }
        return;
    }

    __shared__ float red[16];
    const float* row = (mode == 0) ? q + (size_t)blockIdx.x * DIM
                                   : kv + (size_t)blockIdx.x * (2 * DIM);
    float x0 = row[tid];
    float x1 = row[tid + 256];
    float s  = x0 + x1;
    float sq = x0 * x0 + x1 * x1;
    #pragma unroll
    for (int o = 16; o > 0; o >>= 1) {
        s  += __shfl_xor_sync(0xffffffffu, s,  o);
        sq += __shfl_xor_sync(0xffffffffu, sq, o);
    }
    if ((tid & 31) == 0) { red[tid >> 5] = s; red[8 + (tid >> 5)] = sq; }
    __syncthreads();
    if (tid < 32) {
        float vs = (tid < 8) ? red[tid] : 0.0f;
        float vq = (tid < 8) ? red[8 + tid] : 0.0f;
        #pragma unroll
        for (int o = 4; o > 0; o >>= 1) {
            vs += __shfl_xor_sync(0xffffffffu, vs, o);
            vq += __shfl_xor_sync(0xffffffffu, vq, o);
        }
        if (tid == 0) { red[0] = vs; red[1] = vq; }
    }
    __syncthreads();
    float mean = red[0] * (1.0f / 512.0f);
    float var  = red[1] * (1.0f / 512.0f) - mean * mean;
    float rstd = rsqrtf(var + LN_EPS);
    float y0 = (x0 - mean) * rstd * g[tid]       + b[tid];
    float y1 = (x1 - mean) * rstd * g[tid + 256] + b[tid + 256];
    __half* hr = (mode == 0) ? qh + (size_t)blockIdx.x * DIM
                             : kh + (size_t)blockIdx.x * DIM;
    hr[tid]       = __float2half(y0);
    hr[tid + 256] = __float2half(y1);
}

/* ---------------- softmax(4096) fp32 -> fp16 ---------------- */
__global__ __launch_bounds__(256) void softmax_h(
    const float* __restrict__ S, __half* __restrict__ ph)
{
    __shared__ float red[8];
    const float* row = S + (size_t)blockIdx.x * SEQ;
    __half* hr = ph + (size_t)blockIdx.x * SEQ;
    int tid = threadIdx.x;
    float v[16];
    float mx = -1e30f;
    #pragma unroll
    for (int i = 0; i < 16; i++) { v[i] = row[tid + i * 256]; mx = fmaxf(mx, v[i]); }
    #pragma unroll
    for (int o = 16; o > 0; o >>= 1) mx = fmaxf(mx, __shfl_xor_sync(0xffffffffu, mx, o));
    if ((tid & 31) == 0) red[tid >> 5] = mx;
    __syncthreads();
    if (tid < 32) {
        float m = (tid < 8) ? red[tid] : -1e30f;
        #pragma unroll
        for (int o = 4; o > 0; o >>= 1) m = fmaxf(m, __shfl_xor_sync(0xffffffffu, m, o));
        if (tid == 0) red[0] = m;
    }
    __syncthreads();
    mx = red[0];
    __syncthreads();
    float s = 0.0f;
    #pragma unroll
    for (int i = 0; i < 16; i++) { v[i] = __expf(v[i] - mx); s += v[i]; }
    #pragma unroll
    for (int o = 16; o > 0; o >>= 1) s += __shfl_xor_sync(0xffffffffu, s, o);
    if ((tid & 31) == 0) red[tid >> 5] = s;
    __syncthreads();
    if (tid < 32) {
        float m = (tid < 8) ? red[tid] : 0.0f;
        #pragma unroll
        for (int o = 4; o > 0; o >>= 1) m += __shfl_xor_sync(0xffffffffu, m, o);
        if (tid == 0) red[0] = m;
    }
    __syncthreads();
    float inv = 1.0f / red[0];
    #pragma unroll
    for (int i = 0; i < 16; i += 2) {
        __half2 h2;
        h2.x = __float2half(v[i] * inv);
        h2.y = __float2half(v[i + 1] * inv);
        /* elements i*256 apart are not adjacent; store singly */
        hr[tid + i * 256]       = h2.x;
        hr[tid + (i + 1) * 256] = h2.y;
    }
}

/* ---------------- launcher ---------------- */
#define SMEM_P 81920u      /* proj: 2 stages x 4 tiles, BK=32  */
#define SMEM_A 73728u      /* attn: 2 stages x 2 tiles, BK=64  */

extern "C" void kernel_launch(void* const* d_in, const int* in_sizes, int n_in,
                              void* d_out, int out_size)
{
    const float* x    = (const float*)d_in[0];
    const float* ctx  = (const float*)d_in[1];
    const float* Wq   = (const float*)d_in[2];
    const float* Wkv  = (const float*)d_in[3];
    const float* Wo   = (const float*)d_in[4];
    const float* bo   = (const float*)d_in[5];
    const float* ln_g = (const float*)d_in[6];
    const float* ln_b = (const float*)d_in[7];
    float* out = (float*)d_out;

    float *q, *kv, *S;
    bf16 *xh, *xl, *ch, *cl, *wqth, *wqtl, *wkvth, *wkvtl, *woth, *wotl, *oh, *ol;
    __half *qh, *kh, *vt, *ph;
    cudaGetSymbolAddress((void**)&q,    g_q);
    cudaGetSymbolAddress((void**)&kv,   g_kv);
    cudaGetSymbolAddress((void**)&S,    g_S);
    cudaGetSymbolAddress((void**)&xh,   g_xh);    cudaGetSymbolAddress((void**)&xl,   g_xl);
    cudaGetSymbolAddress((void**)&ch,   g_ch);    cudaGetSymbolAddress((void**)&cl,   g_cl);
    cudaGetSymbolAddress((void**)&wqth, g_wqth);  cudaGetSymbolAddress((void**)&wqtl, g_wqtl);
    cudaGetSymbolAddress((void**)&wkvth,g_wkvth); cudaGetSymbolAddress((void**)&wkvtl,g_wkvtl);
    cudaGetSymbolAddress((void**)&woth, g_woth);  cudaGetSymbolAddress((void**)&wotl, g_wotl);
    cudaGetSymbolAddress((void**)&oh,   g_oh);    cudaGetSymbolAddress((void**)&ol,   g_ol);
    cudaGetSymbolAddress((void**)&qh,   g_qh);    cudaGetSymbolAddress((void**)&kh,   g_kh);
    cudaGetSymbolAddress((void**)&vt,   g_vt);    cudaGetSymbolAddress((void**)&ph,   g_ph);

    cudaFuncSetAttribute(gemm_hilo<bf16,  32, 3, false, false>,
                         cudaFuncAttributeMaxDynamicSharedMemorySize, SMEM_P);
    cudaFuncSetAttribute(gemm_hilo<bf16,  32, 3, false, true>,
                         cudaFuncAttributeMaxDynamicSharedMemorySize, SMEM_P);
    cudaFuncSetAttribute(gemm_hilo<__half,64, 1, false, false>,
                         cudaFuncAttributeMaxDynamicSharedMemorySize, SMEM_A);
    cudaFuncSetAttribute(gemm_hilo<__half,64, 1, true,  false>,
                         cudaFuncAttributeMaxDynamicSharedMemorySize, SMEM_A);

    /* 0: split inputs */
    split_inputs<<<dim3(ROWS * DIM / 4 / 256, 2), 256>>>(x, ctx, xh, xl, ch, cl);
    /* 1: split+transpose all weights */
    wsplit_all<<<1024, 256>>>(Wq, Wkv, Wo, wqth, wqtl, wkvth, wkvtl, woth, wotl);

    /* 2: q = x @ Wq (bf16x3) */
    gemm_hilo<bf16,32,3,false,false><<<dim3(DIM / BN, ROWS / BM, 1), NT, SMEM_P>>>(
        xh, xl, wqth, wqtl, q, nullptr, nullptr, nullptr,
        DIM, DIM, DIM, DIM, 0, 0, 0, 1.0f);

    /* 3: kv = ctx @ Wkv (bf16x3) */
    gemm_hilo<bf16,32,3,false,false><<<dim3(2 * DIM / BN, ROWS / BM, 1), NT, SMEM_P>>>(
        ch, cl, wkvth, wkvtl, kv, nullptr, nullptr, nullptr,
        DIM, DIM, DIM, 2 * DIM, 0, 0, 0, 1.0f);

    /* 4: LN(q)->fp16, LN(k)->fp16, v->v^T fp16 */
    prep_attn<<<dim3(ROWS, 3), 256>>>(q, kv, ln_g, ln_b, qh, kh, vt);

    /* 5: S = scale * q @ k^T (fp16 single pass) */
    gemm_hilo<__half,64,1,false,false><<<dim3(SEQ / BN, SEQ / BM, BATCH), NT, SMEM_A>>>(
        qh, nullptr, kh, nullptr, S, nullptr, nullptr, nullptr,
        DIM, DIM, DIM, SEQ,
        (long long)SEQ * DIM, (long long)SEQ * DIM, (long long)SEQ * SEQ, ATTN_SCALE);

    /* 6: P = softmax(S) -> fp16 */
    softmax_h<<<BATCH * SEQ, 256>>>(S, ph);

    /* 7: O = P @ v (fp16 single pass, split bf16 out) */
    gemm_hilo<__half,64,1,true,false><<<dim3(DIM / BN, SEQ / BM, BATCH), NT, SMEM_A>>>(
        ph, nullptr, vt, nullptr, nullptr, oh, ol, nullptr,
        SEQ, SEQ, SEQ, DIM,
        (long long)SEQ * SEQ, (long long)DIM * SEQ, (long long)SEQ * DIM, 1.0f);

    /* 8: out = O @ Wo + bo (bf16x3) */
    gemm_hilo<bf16,32,3,false,true><<<dim3(DIM / BN, ROWS / BM, 1), NT, SMEM_P>>>(
        oh, ol, woth, wotl, out, nullptr, nullptr, bo,
        DIM, DIM, DIM, DIM, 0, 0, 0, 1.0f);
}

// round 10
// speedup vs baseline: 1.5542x; 1.1176x over previous
#include <cuda_runtime.h>
#include <cuda_bf16.h>
#include <cuda_fp16.h>
#include <mma.h>
#include <cstdint>

using namespace nvcuda;
typedef __nv_bfloat16 bf16;

#define BATCH 4
#define SEQ   4096
#define DIM   512
#define ROWS  16384
#define ATTN_SCALE 0.125f
#define LN_EPS 1e-5f

/* ---------------- scratch (no allocations allowed) ---------------- */
__device__ __align__(256) float g_q [(size_t)ROWS * DIM];
__device__ __align__(256) float g_kv[(size_t)ROWS * 2 * DIM];
__device__ __align__(256) float g_S [(size_t)BATCH * SEQ * SEQ];

__device__ __align__(256) __half g_xh [(size_t)ROWS * DIM];   /* x  hi/lo fp16 */
__device__ __align__(256) __half g_xl [(size_t)ROWS * DIM];
__device__ __align__(256) __half g_ch [(size_t)ROWS * DIM];   /* ctx hi/lo     */
__device__ __align__(256) __half g_cl [(size_t)ROWS * DIM];
__device__ __align__(256) __half g_wqt [DIM * DIM];           /* Wq^T  fp16    */
__device__ __align__(256) __half g_wkvt[2 * DIM * DIM];       /* Wkv^T fp16    */
__device__ __align__(256) bf16 g_woth [DIM * DIM];            /* Wo^T bf16 h/l */
__device__ __align__(256) bf16 g_wotl [DIM * DIM];
__device__ __align__(256) bf16 g_oh [(size_t)ROWS * DIM];
__device__ __align__(256) bf16 g_ol [(size_t)ROWS * DIM];

__device__ __align__(256) __half g_qh [(size_t)ROWS * DIM];          /* single */
__device__ __align__(256) __half g_kh [(size_t)ROWS * DIM];          /* single */
__device__ __align__(256) __half g_vt [(size_t)BATCH * DIM * SEQ];   /* v^T    */
__device__ __align__(256) __half g_ph [(size_t)BATCH * SEQ * SEQ];   /* single */

/* ---------------- cp.async helpers ---------------- */
__device__ __forceinline__ unsigned smem_u32(const void* p) {
    return (unsigned)__cvta_generic_to_shared(p);
}
#define CPA16(dst, src) \
    asm volatile("cp.async.cg.shared.global [%0], [%1], 16;\n" :: "r"(dst), "l"(src))
#define CPCOMMIT() asm volatile("cp.async.commit_group;\n" ::)
template<int N> __device__ __forceinline__ void cpwait() {
    asm volatile("cp.async.wait_group %0;\n" :: "n"(N));
}

/* ---------------- hi/lo GEMM ----------------
 * C[M,N] = alpha * A @ B^T, B given [N,K] row-major.
 * PASSES=3: (Ah+Al)(Bh+Bl) drop AlBl.  PASSES=2: (Ah+Al)Bh.  PASSES=1: Ah Bh.
 * 128x128 tiles, BKT k-chunk, 256 thr, 8 warps of 64x32, 2-stage cp.async.
 */
#define BM 128
#define BN 128
#define NT  256

template<typename T, int BKT>
__device__ __forceinline__ void stage_tile(unsigned sm, const T* g, int ld, int tid) {
    constexpr int CPR = BKT / 8;
    constexpr int AST = BKT + 8;
    #pragma unroll
    for (int i = 0; i < (128 * CPR) / NT; i++) {
        int idx = i * NT + tid;
        int r = idx / CPR, c = (idx % CPR) * 8;
        CPA16(sm + (unsigned)(r * AST + c) * 2, g + (size_t)r * ld + c);
    }
}

template<typename T, int BKT, int PASSES, bool SPLIT, bool BIAS>
__global__ __launch_bounds__(NT, 2) void gemm_hilo(
    const T* __restrict__ Ah, const T* __restrict__ Al,
    const T* __restrict__ Bh, const T* __restrict__ Bl,
    float* __restrict__ C, bf16* __restrict__ Ch, bf16* __restrict__ Cl,
    const float* __restrict__ bias,
    int K, int lda, int ldb, int ldc,
    long long sA, long long sB, long long sC, float alpha)
{
    extern __shared__ char smem[];
    constexpr int AST = BKT + 8;
    constexpr unsigned TSZ = 128u * AST * 2u;
    constexpr unsigned NTILE = (PASSES == 3) ? 4u : (PASSES == 2 ? 3u : 2u);
    constexpr unsigned STG = NTILE * TSZ;

    const int tid  = threadIdx.x;
    const int warp = tid >> 5;
    const int wm = warp >> 2;
    const int wn = warp & 3;
    const int m0 = blockIdx.y * BM;
    const int n0 = blockIdx.x * BN;
    const long long zb = blockIdx.z;
    const unsigned sb0 = smem_u32(smem);

    const T* gAh = Ah + zb * sA + (size_t)m0 * lda;
    const T* gAl = (PASSES >= 2) ? (Al + zb * sA + (size_t)m0 * lda) : nullptr;
    const T* gBh = Bh + zb * sB + (size_t)n0 * ldb;
    const T* gBl = (PASSES == 3) ? (Bl + zb * sB + (size_t)n0 * ldb) : nullptr;

    wmma::fragment<wmma::accumulator, 16, 16, 16, float> acc[4][2];
    #pragma unroll
    for (int i = 0; i < 4; i++)
        #pragma unroll
        for (int j = 0; j < 2; j++)
            wmma::fill_fragment(acc[i][j], 0.0f);

    auto stage = [&](int s, int k0) {
        unsigned sp = sb0 + (unsigned)s * STG;
        stage_tile<T, BKT>(sp, gAh + k0, lda, tid);
        stage_tile<T, BKT>(sp + (NTILE - 1u) * TSZ, gBh + k0, ldb, tid);
        if (PASSES >= 2) stage_tile<T, BKT>(sp + TSZ, gAl + k0, lda, tid);
        if (PASSES == 3) stage_tile<T, BKT>(sp + 2u * TSZ, gBl + k0, ldb, tid);
        CPCOMMIT();
    };

    stage(0, 0);
    int s = 0;
    for (int k0 = 0; k0 < K; k0 += BKT) {
        if (k0 + BKT < K) { stage(s ^ 1, k0 + BKT); cpwait<1>(); }
        else              { cpwait<0>(); }
        __syncthreads();

        T* sAh = (T*)(smem + s * STG);
        T* sAl = (T*)(smem + s * STG + TSZ);
        T* sBl = (T*)(smem + s * STG + 2 * TSZ);
        T* sBh = (T*)(smem + s * STG + (NTILE - 1u) * TSZ);

        #pragma unroll
        for (int kk = 0; kk < BKT; kk += 16) {
            wmma::fragment<wmma::matrix_a, 16, 16, 16, T, wmma::row_major> a[4];
            wmma::fragment<wmma::matrix_b, 16, 16, 16, T, wmma::col_major> bh[2];
            #pragma unroll
            for (int i = 0; i < 4; i++)
                wmma::load_matrix_sync(a[i], sAh + (wm * 64 + i * 16) * AST + kk, AST);
            #pragma unroll
            for (int j = 0; j < 2; j++)
                wmma::load_matrix_sync(bh[j], sBh + (wn * 32 + j * 16) * AST + kk, AST);

            /* pass 1: Ah x Bh */
            #pragma unroll
            for (int i = 0; i < 4; i++)
                #pragma unroll
                for (int j = 0; j < 2; j++)
                    wmma::mma_sync(acc[i][j], a[i], bh[j], acc[i][j]);

            if (PASSES == 3) {
                wmma::fragment<wmma::matrix_b, 16, 16, 16, T, wmma::col_major> bl[2];
                #pragma unroll
                for (int j = 0; j < 2; j++)
                    wmma::load_matrix_sync(bl[j], sBl + (wn * 32 + j * 16) * AST + kk, AST);
                #pragma unroll
                for (int i = 0; i < 4; i++)
                    #pragma unroll
                    for (int j = 0; j < 2; j++)
                        wmma::mma_sync(acc[i][j], a[i], bl[j], acc[i][j]);
            }

            if (PASSES >= 2) {
                #pragma unroll
                for (int i = 0; i < 4; i++)
                    wmma::load_matrix_sync(a[i], sAl + (wm * 64 + i * 16) * AST + kk, AST);
                #pragma unroll
                for (int i = 0; i < 4; i++)
                    #pragma unroll
                    for (int j = 0; j < 2; j++)
                        wmma::mma_sync(acc[i][j], a[i], bh[j], acc[i][j]);
            }
        }
        __syncthreads();
        s ^= 1;
    }

    /* ---- epilogue via smem (128 x 132 fp32) ---- */
    float* cs = (float*)smem;
    #pragma unroll
    for (int i = 0; i < 4; i++)
        #pragma unroll
        for (int j = 0; j < 2; j++) {
            #pragma unroll
            for (int t = 0; t < acc[i][j].num_elements; t++)
                acc[i][j].x[t] *= alpha;
            wmma::store_matrix_sync(cs + (wm * 64 + i * 16) * 132 + wn * 32 + j * 16,
                                    acc[i][j], 132, wmma::mem_row_major);
        }
    __syncthreads();

    #pragma unroll
    for (int it = 0; it < 16; it++) {
        int idx = it * NT + tid;
        int r = idx >> 5, c4 = (idx & 31) * 4;
        float4 v = *(float4*)(cs + r * 132 + c4);
        if (BIAS) {
            v.x += bias[n0 + c4 + 0];
            v.y += bias[n0 + c4 + 1];
            v.z += bias[n0 + c4 + 2];
            v.w += bias[n0 + c4 + 3];
        }
        size_t base = (size_t)zb * sC + (size_t)(m0 + r) * ldc + n0 + c4;
        if (SPLIT) {
            bf16 h0 = __float2bfloat16(v.x), h1 = __float2bfloat16(v.y);
            bf16 h2 = __float2bfloat16(v.z), h3 = __float2bfloat16(v.w);
            __nv_bfloat162 t;
            t.x = h0; t.y = h1; *(__nv_bfloat162*)(Ch + base) = t;
            t.x = h2; t.y = h3; *(__nv_bfloat162*)(Ch + base + 2) = t;
            t.x = __float2bfloat16(v.x - __bfloat162float(h0));
            t.y = __float2bfloat16(v.y - __bfloat162float(h1));
            *(__nv_bfloat162*)(Cl + base) = t;
            t.x = __float2bfloat16(v.z - __bfloat162float(h2));
            t.y = __float2bfloat16(v.w - __bfloat162float(h3));
            *(__nv_bfloat162*)(Cl + base + 2) = t;
        } else {
            *(float4*)(C + base) = v;
        }
    }
}

/* ---------------- fused input split: x/ctx -> fp16 hi/lo ------------- */
__global__ __launch_bounds__(256) void split_inputs(
    const float* __restrict__ x, const float* __restrict__ ctx,
    __half* __restrict__ xh, __half* __restrict__ xl,
    __half* __restrict__ ch, __half* __restrict__ cl)
{
    const float* in = blockIdx.y ? ctx : x;
    __half* h = blockIdx.y ? ch : xh;
    __half* l = blockIdx.y ? cl : xl;
    size_t i = (size_t)blockIdx.x * 256 + threadIdx.x;
    float4 v = ((const float4*)in)[i];
    __half h0 = __float2half(v.x), h1 = __float2half(v.y);
    __half h2 = __float2half(v.z), h3 = __float2half(v.w);
    __half2 t;
    t.x = h0; t.y = h1; *(__half2*)(h + i * 4) = t;
    t.x = h2; t.y = h3; *(__half2*)(h + i * 4 + 2) = t;
    t.x = __float2half(v.x - __half2float(h0));
    t.y = __float2half(v.y - __half2float(h1));
    *(__half2*)(l + i * 4) = t;
    t.x = __float2half(v.z - __half2float(h2));
    t.y = __float2half(v.w - __half2float(h3));
    *(__half2*)(l + i * 4 + 2) = t;
}

/* ---------------- weights: Wq/Wkv -> W^T fp16 single; Wo -> bf16 h/l ----- */
__global__ __launch_bounds__(256) void wsplit_all(
    const float* __restrict__ Wq, const float* __restrict__ Wkv, const float* __restrict__ Wo,
    __half* __restrict__ wqt, __half* __restrict__ wkvt,
    bf16* __restrict__ woth, bf16* __restrict__ wotl)
{
    __shared__ float t[32][33];
    int bx = blockIdx.x;
    const float* W; int N, tidx, kind;
    __half* th = nullptr;
    if (bx < 256)      { W = Wq;  th = wqt;  N = DIM;     tidx = bx;       kind = 0; }
    else if (bx < 768) { W = Wkv; th = wkvt; N = 2 * DIM; tidx = bx - 256; kind = 0; }
    else               { W = Wo;             N = DIM;     tidx = bx - 768; kind = 1; }
    int nT = N / 32;
    int n0 = (tidx % nT) * 32, k0 = (tidx / nT) * 32;
    int tx = threadIdx.x & 31, ty = threadIdx.x >> 5;
    #pragma unroll
    for (int j = 0; j < 4; j++) {
        int r = ty + j * 8;
        t[r][tx] = W[(size_t)(k0 + r) * N + n0 + tx];
    }
    __syncthreads();
    #pragma unroll
    for (int j = 0; j < 4; j++) {
        int r = ty + j * 8;
        float v = t[tx][r];
        size_t o = (size_t)(n0 + r) * DIM + k0 + tx;
        if (kind == 0) {
            th[o] = __float2half(v);
        } else {
            bf16 h = __float2bfloat16(v);
            woth[o] = h;
            wotl[o] = __float2bfloat16(v - __bfloat162float(h));
        }
    }
}

/* ---------------- fused attention prep: LN(q)->fp16, LN(k)->fp16,
                    v -> v^T fp16 ---------------- */
__global__ __launch_bounds__(256) void prep_attn(
    const float* __restrict__ q, const float* __restrict__ kv,
    const float* __restrict__ g, const float* __restrict__ b,
    __half* __restrict__ qh, __half* __restrict__ kh, __half* __restrict__ vt)
{
    const int mode = blockIdx.y;
    int tid = threadIdx.x;

    if (mode == 2) {                     /* v transpose, fp16 single */
        if (blockIdx.x >= 8192) return;
        __shared__ float t[32][33];
        int bx = blockIdx.x;
        int bb = bx >> 11;
        int rem = bx & 2047;
        int d0 = (rem >> 7) * 32;
        int m0 = (rem & 127) * 32;
        int tx = tid & 31, ty = tid >> 5;
        const float* src = kv + ((size_t)bb * SEQ) * (2 * DIM) + DIM;
        #pragma unroll
        for (int j = 0; j < 4; j++) {
            int r = ty + j * 8;
            t[r][tx] = src[(size_t)(m0 + r) * (2 * DIM) + d0 + tx];
        }
        __syncthreads();
        #pragma unroll
        for (int j = 0; j < 4; j++) {
            int r = ty + j * 8;
            vt[((size_t)bb * DIM + d0 + r) * SEQ + m0 + tx] = __float2half(t[tx][r]);
        }
        return;
    }

    __shared__ float red[16];
    const float* row = (mode == 0) ? q + (size_t)blockIdx.x * DIM
                                   : kv + (size_t)blockIdx.x * (2 * DIM);
    float x0 = row[tid];
    float x1 = row[tid + 256];
    float s  = x0 + x1;
    float sq = x0 * x0 + x1 * x1;
    #pragma unroll
    for (int o = 16; o > 0; o >>= 1) {
        s  += __shfl_xor_sync(0xffffffffu, s,  o);
        sq += __shfl_xor_sync(0xffffffffu, sq, o);
    }
    if ((tid & 31) == 0) { red[tid >> 5] = s; red[8 + (tid >> 5)] = sq; }
    __syncthreads();
    if (tid < 32) {
        float vs = (tid < 8) ? red[tid] : 0.0f;
        float vq = (tid < 8) ? red[8 + tid] : 0.0f;
        #pragma unroll
        for (int o = 4; o > 0; o >>= 1) {
            vs += __shfl_xor_sync(0xffffffffu, vs, o);
            vq += __shfl_xor_sync(0xffffffffu, vq, o);
        }
        if (tid == 0) { red[0] = vs; red[1] = vq; }
    }
    __syncthreads();
    float mean = red[0] * (1.0f / 512.0f);
    float var  = red[1] * (1.0f / 512.0f) - mean * mean;
    float rstd = rsqrtf(var + LN_EPS);
    float y0 = (x0 - mean) * rstd * g[tid]       + b[tid];
    float y1 = (x1 - mean) * rstd * g[tid + 256] + b[tid + 256];
    __half* hr = (mode == 0) ? qh + (size_t)blockIdx.x * DIM
                             : kh + (size_t)blockIdx.x * DIM;
    hr[tid]       = __float2half(y0);
    hr[tid + 256] = __float2half(y1);
}

/* ---------------- softmax(4096) fp32 -> fp16 ---------------- */
__global__ __launch_bounds__(256) void softmax_h(
    const float* __restrict__ S, __half* __restrict__ ph)
{
    __shared__ float red[8];
    const float* row = S + (size_t)blockIdx.x * SEQ;
    __half* hr = ph + (size_t)blockIdx.x * SEQ;
    int tid = threadIdx.x;
    float v[16];
    float mx = -1e30f;
    #pragma unroll
    for (int i = 0; i < 16; i++) { v[i] = row[tid + i * 256]; mx = fmaxf(mx, v[i]); }
    #pragma unroll
    for (int o = 16; o > 0; o >>= 1) mx = fmaxf(mx, __shfl_xor_sync(0xffffffffu, mx, o));
    if ((tid & 31) == 0) red[tid >> 5] = mx;
    __syncthreads();
    if (tid < 32) {
        float m = (tid < 8) ? red[tid] : -1e30f;
        #pragma unroll
        for (int o = 4; o > 0; o >>= 1) m = fmaxf(m, __shfl_xor_sync(0xffffffffu, m, o));
        if (tid == 0) red[0] = m;
    }
    __syncthreads();
    mx = red[0];
    __syncthreads();
    float s = 0.0f;
    #pragma unroll
    for (int i = 0; i < 16; i++) { v[i] = __expf(v[i] - mx); s += v[i]; }
    #pragma unroll
    for (int o = 16; o > 0; o >>= 1) s += __shfl_xor_sync(0xffffffffu, s, o);
    if ((tid & 31) == 0) red[tid >> 5] = s;
    __syncthreads();
    if (tid < 32) {
        float m = (tid < 8) ? red[tid] : 0.0f;
        #pragma unroll
        for (int o = 4; o > 0; o >>= 1) m += __shfl_xor_sync(0xffffffffu, m, o);
        if (tid == 0) red[0] = m;
    }
    __syncthreads();
    float inv = 1.0f / red[0];
    #pragma unroll
    for (int i = 0; i < 16; i++)
        hr[tid + i * 256] = __float2half(v[i] * inv);
}

/* ---------------- launcher ---------------- */
#define SMEM_P2 69632u     /* fp16x2 proj: max(2x3x10240, epilogue 67584) */
#define SMEM_P3 81920u     /* bf16x3 out-proj: 2 stages x 4 tiles         */
#define SMEM_A  73728u     /* attn: 2 stages x 2 tiles, BK=64             */

extern "C" void kernel_launch(void* const* d_in, const int* in_sizes, int n_in,
                              void* d_out, int out_size)
{
    const float* x    = (const float*)d_in[0];
    const float* ctx  = (const float*)d_in[1];
    const float* Wq   = (const float*)d_in[2];
    const float* Wkv  = (const float*)d_in[3];
    const float* Wo   = (const float*)d_in[4];
    const float* bo   = (const float*)d_in[5];
    const float* ln_g = (const float*)d_in[6];
    const float* ln_b = (const float*)d_in[7];
    float* out = (float*)d_out;

    float *q, *kv, *S;
    bf16 *woth, *wotl, *oh, *ol;
    __half *xh, *xl, *ch, *cl, *wqt, *wkvt, *qh, *kh, *vt, *ph;
    cudaGetSymbolAddress((void**)&q,    g_q);
    cudaGetSymbolAddress((void**)&kv,   g_kv);
    cudaGetSymbolAddress((void**)&S,    g_S);
    cudaGetSymbolAddress((void**)&xh,   g_xh);    cudaGetSymbolAddress((void**)&xl,   g_xl);
    cudaGetSymbolAddress((void**)&ch,   g_ch);    cudaGetSymbolAddress((void**)&cl,   g_cl);
    cudaGetSymbolAddress((void**)&wqt,  g_wqt);   cudaGetSymbolAddress((void**)&wkvt, g_wkvt);
    cudaGetSymbolAddress((void**)&woth, g_woth);  cudaGetSymbolAddress((void**)&wotl, g_wotl);
    cudaGetSymbolAddress((void**)&oh,   g_oh);    cudaGetSymbolAddress((void**)&ol,   g_ol);
    cudaGetSymbolAddress((void**)&qh,   g_qh);    cudaGetSymbolAddress((void**)&kh,   g_kh);
    cudaGetSymbolAddress((void**)&vt,   g_vt);    cudaGetSymbolAddress((void**)&ph,   g_ph);

    cudaFuncSetAttribute(gemm_hilo<__half,32, 2, false, false>,
                         cudaFuncAttributeMaxDynamicSharedMemorySize, SMEM_P2);
    cudaFuncSetAttribute(gemm_hilo<bf16,  32, 3, false, true>,
                         cudaFuncAttributeMaxDynamicSharedMemorySize, SMEM_P3);
    cudaFuncSetAttribute(gemm_hilo<__half,64, 1, false, false>,
                         cudaFuncAttributeMaxDynamicSharedMemorySize, SMEM_A);
    cudaFuncSetAttribute(gemm_hilo<__half,64, 1, true,  false>,
                         cudaFuncAttributeMaxDynamicSharedMemorySize, SMEM_A);

    /* 0: split inputs to fp16 hi/lo */
    split_inputs<<<dim3(ROWS * DIM / 4 / 256, 2), 256>>>(x, ctx, xh, xl, ch, cl);
    /* 1: weights: Wq/Wkv -> fp16 transpose; Wo -> bf16 hi/lo transpose */
    wsplit_all<<<1024, 256>>>(Wq, Wkv, Wo, wqt, wkvt, woth, wotl);

    /* 2: q = x @ Wq (fp16x2: x split, W single) */
    gemm_hilo<__half,32,2,false,false><<<dim3(DIM / BN, ROWS / BM, 1), NT, SMEM_P2>>>(
        xh, xl, wqt, nullptr, q, nullptr, nullptr, nullptr,
        DIM, DIM, DIM, DIM, 0, 0, 0, 1.0f);

    /* 3: kv = ctx @ Wkv (fp16x2) */
    gemm_hilo<__half,32,2,false,false><<<dim3(2 * DIM / BN, ROWS / BM, 1), NT, SMEM_P2>>>(
        ch, cl, wkvt, nullptr, kv, nullptr, nullptr, nullptr,
        DIM, DIM, DIM, 2 * DIM, 0, 0, 0, 1.0f);

    /* 4: LN(q)->fp16, LN(k)->fp16, v->v^T fp16 */
    prep_attn<<<dim3(ROWS, 3), 256>>>(q, kv, ln_g, ln_b, qh, kh, vt);

    /* 5: S = scale * q @ k^T (fp16 single pass) */
    gemm_hilo<__half,64,1,false,false><<<dim3(SEQ / BN, SEQ / BM, BATCH), NT, SMEM_A>>>(
        qh, nullptr, kh, nullptr, S, nullptr, nullptr, nullptr,
        DIM, DIM, DIM, SEQ,
        (long long)SEQ * DIM, (long long)SEQ * DIM, (long long)SEQ * SEQ, ATTN_SCALE);

    /* 6: P = softmax(S) -> fp16 */
    softmax_h<<<BATCH * SEQ, 256>>>(S, ph);

    /* 7: O = P @ v (fp16 single pass, split bf16 out) */
    gemm_hilo<__half,64,1,true,false><<<dim3(DIM / BN, SEQ / BM, BATCH), NT, SMEM_A>>>(
        ph, nullptr, vt, nullptr, nullptr, oh, ol, nullptr,
        SEQ, SEQ, SEQ, DIM,
        (long long)SEQ * SEQ, (long long)DIM * SEQ, (long long)SEQ * DIM, 1.0f);

    /* 8: out = O @ Wo + bo (bf16x3, exact path) */
    gemm_hilo<bf16,32,3,false,true><<<dim3(DIM / BN, ROWS / BM, 1), NT, SMEM_P3>>>(
        oh, ol, woth, wotl, out, nullptr, nullptr, bo,
        DIM, DIM, DIM, DIM, 0, 0, 0, 1.0f);
}

// round 11
// speedup vs baseline: 1.6331x; 1.0508x over previous
#include <cuda_runtime.h>
#include <cuda_bf16.h>
#include <cuda_fp16.h>
#include <mma.h>
#include <cstdint>

using namespace nvcuda;
typedef __nv_bfloat16 bf16;

#define BATCH 4
#define SEQ   4096
#define DIM   512
#define ROWS  16384
#define ATTN_SCALE 0.125f
#define EXP_SHIFT 11.0f
#define LN_EPS 1e-5f

/* ---------------- scratch (no allocations allowed) ---------------- */
__device__ __align__(256) float g_q [(size_t)ROWS * DIM];
__device__ __align__(256) float g_kv[(size_t)ROWS * 2 * DIM];
__device__ __align__(256) float g_rs[(size_t)BATCH * SEQ];    /* softmax row sums */

__device__ __align__(256) __half g_xh [(size_t)ROWS * DIM];
__device__ __align__(256) __half g_xl [(size_t)ROWS * DIM];
__device__ __align__(256) __half g_ch [(size_t)ROWS * DIM];
__device__ __align__(256) __half g_cl [(size_t)ROWS * DIM];
__device__ __align__(256) __half g_wqt [DIM * DIM];
__device__ __align__(256) __half g_wkvt[2 * DIM * DIM];
__device__ __align__(256) bf16 g_woth [DIM * DIM];
__device__ __align__(256) bf16 g_wotl [DIM * DIM];
__device__ __align__(256) bf16 g_oh [(size_t)ROWS * DIM];
__device__ __align__(256) bf16 g_ol [(size_t)ROWS * DIM];

__device__ __align__(256) __half g_qh [(size_t)ROWS * DIM];
__device__ __align__(256) __half g_kh [(size_t)ROWS * DIM];
__device__ __align__(256) __half g_vt [(size_t)BATCH * DIM * SEQ];
__device__ __align__(256) __half g_ph [(size_t)BATCH * SEQ * SEQ]; /* exp(S-11) fp16 */

/* ---------------- cp.async helpers ---------------- */
__device__ __forceinline__ unsigned smem_u32(const void* p) {
    return (unsigned)__cvta_generic_to_shared(p);
}
#define CPA16(dst, src) \
    asm volatile("cp.async.cg.shared.global [%0], [%1], 16;\n" :: "r"(dst), "l"(src))
#define CPCOMMIT() asm volatile("cp.async.commit_group;\n" ::)
template<int N> __device__ __forceinline__ void cpwait() {
    asm volatile("cp.async.wait_group %0;\n" :: "n"(N));
}

/* ---------------- hi/lo GEMM ----------------
 * C[M,N] = alpha * A @ B^T, B given [N,K] row-major.
 * PASSES: 3 = (Ah+Al)(Bh+Bl) drop AlBl; 2 = (Ah+Al)Bh; 1 = Ah Bh.
 * EPI: 0 = fp32 store (+bias); 2 = exp->fp16 store + rowsum atomics;
 *      3 = divide-by-rowsum then bf16 hi/lo split store.
 * 128x128 tiles, BKT k-chunk, 256 thr, 8 warps of 64x32, 2-stage cp.async.
 */
#define BM 128
#define BN 128
#define NT  256

template<typename T, int BKT>
__device__ __forceinline__ void stage_tile(unsigned sm, const T* g, int ld, int tid) {
    constexpr int CPR = BKT / 8;
    constexpr int AST = BKT + 8;
    #pragma unroll
    for (int i = 0; i < (128 * CPR) / NT; i++) {
        int idx = i * NT + tid;
        int r = idx / CPR, c = (idx % CPR) * 8;
        CPA16(sm + (unsigned)(r * AST + c) * 2, g + (size_t)r * ld + c);
    }
}

template<typename T, int BKT, int PASSES, int EPI, bool BIAS>
__global__ __launch_bounds__(NT, 2) void gemm_hilo(
    const T* __restrict__ Ah, const T* __restrict__ Al,
    const T* __restrict__ Bh, const T* __restrict__ Bl,
    float* __restrict__ C, bf16* __restrict__ Ch, bf16* __restrict__ Cl,
    __half* __restrict__ Hout, float* __restrict__ rs,
    const float* __restrict__ bias,
    int K, int lda, int ldb, int ldc,
    long long sA, long long sB, long long sC, float alpha)
{
    extern __shared__ char smem[];
    constexpr int AST = BKT + 8;
    constexpr unsigned TSZ = 128u * AST * 2u;
    constexpr unsigned NTILE = (PASSES == 3) ? 4u : (PASSES == 2 ? 3u : 2u);
    constexpr unsigned STG = NTILE * TSZ;

    const int tid  = threadIdx.x;
    const int warp = tid >> 5;
    const int wm = warp >> 2;
    const int wn = warp & 3;
    const int m0 = blockIdx.y * BM;
    const int n0 = blockIdx.x * BN;
    const long long zb = blockIdx.z;
    const unsigned sb0 = smem_u32(smem);

    const T* gAh = Ah + zb * sA + (size_t)m0 * lda;
    const T* gAl = (PASSES >= 2) ? (Al + zb * sA + (size_t)m0 * lda) : nullptr;
    const T* gBh = Bh + zb * sB + (size_t)n0 * ldb;
    const T* gBl = (PASSES == 3) ? (Bl + zb * sB + (size_t)n0 * ldb) : nullptr;

    wmma::fragment<wmma::accumulator, 16, 16, 16, float> acc[4][2];
    #pragma unroll
    for (int i = 0; i < 4; i++)
        #pragma unroll
        for (int j = 0; j < 2; j++)
            wmma::fill_fragment(acc[i][j], 0.0f);

    auto stage = [&](int s, int k0) {
        unsigned sp = sb0 + (unsigned)s * STG;
        stage_tile<T, BKT>(sp, gAh + k0, lda, tid);
        stage_tile<T, BKT>(sp + (NTILE - 1u) * TSZ, gBh + k0, ldb, tid);
        if (PASSES >= 2) stage_tile<T, BKT>(sp + TSZ, gAl + k0, lda, tid);
        if (PASSES == 3) stage_tile<T, BKT>(sp + 2u * TSZ, gBl + k0, ldb, tid);
        CPCOMMIT();
    };

    stage(0, 0);
    int s = 0;
    for (int k0 = 0; k0 < K; k0 += BKT) {
        if (k0 + BKT < K) { stage(s ^ 1, k0 + BKT); cpwait<1>(); }
        else              { cpwait<0>(); }
        __syncthreads();

        T* sAh = (T*)(smem + s * STG);
        T* sAl = (T*)(smem + s * STG + TSZ);
        T* sBl = (T*)(smem + s * STG + 2 * TSZ);
        T* sBh = (T*)(smem + s * STG + (NTILE - 1u) * TSZ);

        #pragma unroll
        for (int kk = 0; kk < BKT; kk += 16) {
            wmma::fragment<wmma::matrix_a, 16, 16, 16, T, wmma::row_major> a[4];
            wmma::fragment<wmma::matrix_b, 16, 16, 16, T, wmma::col_major> bh[2];
            #pragma unroll
            for (int i = 0; i < 4; i++)
                wmma::load_matrix_sync(a[i], sAh + (wm * 64 + i * 16) * AST + kk, AST);
            #pragma unroll
            for (int j = 0; j < 2; j++)
                wmma::load_matrix_sync(bh[j], sBh + (wn * 32 + j * 16) * AST + kk, AST);

            #pragma unroll
            for (int i = 0; i < 4; i++)
                #pragma unroll
                for (int j = 0; j < 2; j++)
                    wmma::mma_sync(acc[i][j], a[i], bh[j], acc[i][j]);

            if (PASSES == 3) {
                wmma::fragment<wmma::matrix_b, 16, 16, 16, T, wmma::col_major> bl[2];
                #pragma unroll
                for (int j = 0; j < 2; j++)
                    wmma::load_matrix_sync(bl[j], sBl + (wn * 32 + j * 16) * AST + kk, AST);
                #pragma unroll
                for (int i = 0; i < 4; i++)
                    #pragma unroll
                    for (int j = 0; j < 2; j++)
                        wmma::mma_sync(acc[i][j], a[i], bl[j], acc[i][j]);
            }

            if (PASSES >= 2) {
                #pragma unroll
                for (int i = 0; i < 4; i++)
                    wmma::load_matrix_sync(a[i], sAl + (wm * 64 + i * 16) * AST + kk, AST);
                #pragma unroll
                for (int i = 0; i < 4; i++)
                    #pragma unroll
                    for (int j = 0; j < 2; j++)
                        wmma::mma_sync(acc[i][j], a[i], bh[j], acc[i][j]);
            }
        }
        __syncthreads();
        s ^= 1;
    }

    /* ---- epilogue via smem (128 x 132 fp32) ---- */
    float* cs = (float*)smem;
    #pragma unroll
    for (int i = 0; i < 4; i++)
        #pragma unroll
        for (int j = 0; j < 2; j++) {
            #pragma unroll
            for (int t = 0; t < acc[i][j].num_elements; t++)
                acc[i][j].x[t] *= alpha;
            wmma::store_matrix_sync(cs + (wm * 64 + i * 16) * 132 + wn * 32 + j * 16,
                                    acc[i][j], 132, wmma::mem_row_major);
        }
    __syncthreads();

    #pragma unroll
    for (int it = 0; it < 16; it++) {
        int idx = it * NT + tid;
        int r = idx >> 5, c4 = (idx & 31) * 4;   /* whole warp shares row r */
        float4 v = *(float4*)(cs + r * 132 + c4);

        if (EPI == 2) {
            /* exp(S - shift) -> fp16, accumulate row sum */
            float e0 = __expf(v.x - EXP_SHIFT);
            float e1 = __expf(v.y - EXP_SHIFT);
            float e2 = __expf(v.z - EXP_SHIFT);
            float e3 = __expf(v.w - EXP_SHIFT);
            size_t base = (size_t)zb * sC + (size_t)(m0 + r) * ldc + n0 + c4;
            __half2 t;
            t.x = __float2half(e0); t.y = __float2half(e1);
            *(__half2*)(Hout + base) = t;
            t.x = __float2half(e2); t.y = __float2half(e3);
            *(__half2*)(Hout + base + 2) = t;
            float s4 = (e0 + e1) + (e2 + e3);
            #pragma unroll
            for (int o = 16; o > 0; o >>= 1)
                s4 += __shfl_xor_sync(0xffffffffu, s4, o);
            if ((tid & 31) == 0)
                atomicAdd(&rs[(size_t)zb * SEQ + m0 + r], s4);
        } else if (EPI == 3) {
            /* normalize by row sum, bf16 hi/lo split store */
            float zi = __fdividef(1.0f, rs[(size_t)zb * SEQ + m0 + r]);
            v.x *= zi; v.y *= zi; v.z *= zi; v.w *= zi;
            size_t base = (size_t)zb * sC + (size_t)(m0 + r) * ldc + n0 + c4;
            bf16 h0 = __float2bfloat16(v.x), h1 = __float2bfloat16(v.y);
            bf16 h2 = __float2bfloat16(v.z), h3 = __float2bfloat16(v.w);
            __nv_bfloat162 t;
            t.x = h0; t.y = h1; *(__nv_bfloat162*)(Ch + base) = t;
            t.x = h2; t.y = h3; *(__nv_bfloat162*)(Ch + base + 2) = t;
            t.x = __float2bfloat16(v.x - __bfloat162float(h0));
            t.y = __float2bfloat16(v.y - __bfloat162float(h1));
            *(__nv_bfloat162*)(Cl + base) = t;
            t.x = __float2bfloat16(v.z - __bfloat162float(h2));
            t.y = __float2bfloat16(v.w - __bfloat162float(h3));
            *(__nv_bfloat162*)(Cl + base + 2) = t;
        } else {
            if (BIAS) {
                v.x += bias[n0 + c4 + 0];
                v.y += bias[n0 + c4 + 1];
                v.z += bias[n0 + c4 + 2];
                v.w += bias[n0 + c4 + 3];
            }
            size_t base = (size_t)zb * sC + (size_t)(m0 + r) * ldc + n0 + c4;
            *(float4*)(C + base) = v;
        }
    }
}

/* ---------------- zero the rowsum accumulator ---------------- */
__global__ __launch_bounds__(256) void zero_rs(float* __restrict__ rs)
{
    rs[blockIdx.x * 256 + threadIdx.x] = 0.0f;
}

/* ---------------- fused input split: x/ctx -> fp16 hi/lo ------------- */
__global__ __launch_bounds__(256) void split_inputs(
    const float* __restrict__ x, const float* __restrict__ ctx,
    __half* __restrict__ xh, __half* __restrict__ xl,
    __half* __restrict__ ch, __half* __restrict__ cl)
{
    const float* in = blockIdx.y ? ctx : x;
    __half* h = blockIdx.y ? ch : xh;
    __half* l = blockIdx.y ? cl : xl;
    size_t i = (size_t)blockIdx.x * 256 + threadIdx.x;
    float4 v = ((const float4*)in)[i];
    __half h0 = __float2half(v.x), h1 = __float2half(v.y);
    __half h2 = __float2half(v.z), h3 = __float2half(v.w);
    __half2 t;
    t.x = h0; t.y = h1; *(__half2*)(h + i * 4) = t;
    t.x = h2; t.y = h3; *(__half2*)(h + i * 4 + 2) = t;
    t.x = __float2half(v.x - __half2float(h0));
    t.y = __float2half(v.y - __half2float(h1));
    *(__half2*)(l + i * 4) = t;
    t.x = __float2half(v.z - __half2float(h2));
    t.y = __float2half(v.w - __half2float(h3));
    *(__half2*)(l + i * 4 + 2) = t;
}

/* ---------------- weights: Wq/Wkv -> W^T fp16 single; Wo -> bf16 h/l ----- */
__global__ __launch_bounds__(256) void wsplit_all(
    const float* __restrict__ Wq, const float* __restrict__ Wkv, const float* __restrict__ Wo,
    __half* __restrict__ wqt, __half* __restrict__ wkvt,
    bf16* __restrict__ woth, bf16* __restrict__ wotl)
{
    __shared__ float t[32][33];
    int bx = blockIdx.x;
    const float* W; int N, tidx, kind;
    __half* th = nullptr;
    if (bx < 256)      { W = Wq;  th = wqt;  N = DIM;     tidx = bx;       kind = 0; }
    else if (bx < 768) { W = Wkv; th = wkvt; N = 2 * DIM; tidx = bx - 256; kind = 0; }
    else               { W = Wo;             N = DIM;     tidx = bx - 768; kind = 1; }
    int nT = N / 32;
    int n0 = (tidx % nT) * 32, k0 = (tidx / nT) * 32;
    int tx = threadIdx.x & 31, ty = threadIdx.x >> 5;
    #pragma unroll
    for (int j = 0; j < 4; j++) {
        int r = ty + j * 8;
        t[r][tx] = W[(size_t)(k0 + r) * N + n0 + tx];
    }
    __syncthreads();
    #pragma unroll
    for (int j = 0; j < 4; j++) {
        int r = ty + j * 8;
        float v = t[tx][r];
        size_t o = (size_t)(n0 + r) * DIM + k0 + tx;
        if (kind == 0) {
            th[o] = __float2half(v);
        } else {
            bf16 h = __float2bfloat16(v);
            woth[o] = h;
            wotl[o] = __float2bfloat16(v - __bfloat162float(h));
        }
    }
}

/* ---------------- fused attention prep ---------------- */
__global__ __launch_bounds__(256) void prep_attn(
    const float* __restrict__ q, const float* __restrict__ kv,
    const float* __restrict__ g, const float* __restrict__ b,
    __half* __restrict__ qh, __half* __restrict__ kh, __half* __restrict__ vt)
{
    const int mode = blockIdx.y;
    int tid = threadIdx.x;

    if (mode == 2) {                     /* v transpose, fp16 single */
        if (blockIdx.x >= 8192) return;
        __shared__ float t[32][33];
        int bx = blockIdx.x;
        int bb = bx >> 11;
        int rem = bx & 2047;
        int d0 = (rem >> 7) * 32;
        int m0 = (rem & 127) * 32;
        int tx = tid & 31, ty = tid >> 5;
        const float* src = kv + ((size_t)bb * SEQ) * (2 * DIM) + DIM;
        #pragma unroll
        for (int j = 0; j < 4; j++) {
            int r = ty + j * 8;
            t[r][tx] = src[(size_t)(m0 + r) * (2 * DIM) + d0 + tx];
        }
        __syncthreads();
        #pragma unroll
        for (int j = 0; j < 4; j++) {
            int r = ty + j * 8;
            vt[((size_t)bb * DIM + d0 + r) * SEQ + m0 + tx] = __float2half(t[tx][r]);
        }
        return;
    }

    __shared__ float red[16];
    const float* row = (mode == 0) ? q + (size_t)blockIdx.x * DIM
                                   : kv + (size_t)blockIdx.x * (2 * DIM);
    float x0 = row[tid];
    float x1 = row[tid + 256];
    float s  = x0 + x1;
    float sq = x0 * x0 + x1 * x1;
    #pragma unroll
    for (int o = 16; o > 0; o >>= 1) {
        s  += __shfl_xor_sync(0xffffffffu, s,  o);
        sq += __shfl_xor_sync(0xffffffffu, sq, o);
    }
    if ((tid & 31) == 0) { red[tid >> 5] = s; red[8 + (tid >> 5)] = sq; }
    __syncthreads();
    if (tid < 32) {
        float vs = (tid < 8) ? red[tid] : 0.0f;
        float vq = (tid < 8) ? red[8 + tid] : 0.0f;
        #pragma unroll
        for (int o = 4; o > 0; o >>= 1) {
            vs += __shfl_xor_sync(0xffffffffu, vs, o);
            vq += __shfl_xor_sync(0xffffffffu, vq, o);
        }
        if (tid == 0) { red[0] = vs; red[1] = vq; }
    }
    __syncthreads();
    float mean = red[0] * (1.0f / 512.0f);
    float var  = red[1] * (1.0f / 512.0f) - mean * mean;
    float rstd = rsqrtf(var + LN_EPS);
    float y0 = (x0 - mean) * rstd * g[tid]       + b[tid];
    float y1 = (x1 - mean) * rstd * g[tid + 256] + b[tid + 256];
    __half* hr = (mode == 0) ? qh + (size_t)blockIdx.x * DIM
                             : kh + (size_t)blockIdx.x * DIM;
    hr[tid]       = __float2half(y0);
    hr[tid + 256] = __float2half(y1);
}

/* ---------------- launcher ---------------- */
#define SMEM_P2 69632u     /* fp16x2 proj: max(stages 61440, epilogue 67584) */
#define SMEM_P3 81920u     /* bf16x3 out-proj: 2 stages x 4 tiles            */
#define SMEM_A  73728u     /* attn: 2 stages x 2 tiles, BK=64                */

extern "C" void kernel_launch(void* const* d_in, const int* in_sizes, int n_in,
                              void* d_out, int out_size)
{
    const float* x    = (const float*)d_in[0];
    const float* ctx  = (const float*)d_in[1];
    const float* Wq   = (const float*)d_in[2];
    const float* Wkv  = (const float*)d_in[3];
    const float* Wo   = (const float*)d_in[4];
    const float* bo   = (const float*)d_in[5];
    const float* ln_g = (const float*)d_in[6];
    const float* ln_b = (const float*)d_in[7];
    float* out = (float*)d_out;

    float *q, *kv, *rs;
    bf16 *woth, *wotl, *oh, *ol;
    __half *xh, *xl, *ch, *cl, *wqt, *wkvt, *qh, *kh, *vt, *ph;
    cudaGetSymbolAddress((void**)&q,    g_q);
    cudaGetSymbolAddress((void**)&kv,   g_kv);
    cudaGetSymbolAddress((void**)&rs,   g_rs);
    cudaGetSymbolAddress((void**)&xh,   g_xh);    cudaGetSymbolAddress((void**)&xl,   g_xl);
    cudaGetSymbolAddress((void**)&ch,   g_ch);    cudaGetSymbolAddress((void**)&cl,   g_cl);
    cudaGetSymbolAddress((void**)&wqt,  g_wqt);   cudaGetSymbolAddress((void**)&wkvt, g_wkvt);
    cudaGetSymbolAddress((void**)&woth, g_woth);  cudaGetSymbolAddress((void**)&wotl, g_wotl);
    cudaGetSymbolAddress((void**)&oh,   g_oh);    cudaGetSymbolAddress((void**)&ol,   g_ol);
    cudaGetSymbolAddress((void**)&qh,   g_qh);    cudaGetSymbolAddress((void**)&kh,   g_kh);
    cudaGetSymbolAddress((void**)&vt,   g_vt);    cudaGetSymbolAddress((void**)&ph,   g_ph);

    cudaFuncSetAttribute(gemm_hilo<__half,32, 2, 0, false>,
                         cudaFuncAttributeMaxDynamicSharedMemorySize, SMEM_P2);
    cudaFuncSetAttribute(gemm_hilo<bf16,  32, 3, 0, true>,
                         cudaFuncAttributeMaxDynamicSharedMemorySize, SMEM_P3);
    cudaFuncSetAttribute(gemm_hilo<__half,64, 1, 2, false>,
                         cudaFuncAttributeMaxDynamicSharedMemorySize, SMEM_A);
    cudaFuncSetAttribute(gemm_hilo<__half,64, 1, 3, false>,
                         cudaFuncAttributeMaxDynamicSharedMemorySize, SMEM_A);

    /* 0: split inputs to fp16 hi/lo */
    split_inputs<<<dim3(ROWS * DIM / 4 / 256, 2), 256>>>(x, ctx, xh, xl, ch, cl);
    /* 1: weights: Wq/Wkv -> fp16 transpose; Wo -> bf16 hi/lo transpose */
    wsplit_all<<<1024, 256>>>(Wq, Wkv, Wo, wqt, wkvt, woth, wotl);
    /* 2: zero softmax row sums */
    zero_rs<<<(BATCH * SEQ) / 256, 256>>>(rs);

    /* 3: q = x @ Wq (fp16x2) */
    gemm_hilo<__half,32,2,0,false><<<dim3(DIM / BN, ROWS / BM, 1), NT, SMEM_P2>>>(
        xh, xl, wqt, nullptr, q, nullptr, nullptr, nullptr, nullptr, nullptr,
        DIM, DIM, DIM, DIM, 0, 0, 0, 1.0f);

    /* 4: kv = ctx @ Wkv (fp16x2) */
    gemm_hilo<__half,32,2,0,false><<<dim3(2 * DIM / BN, ROWS / BM, 1), NT, SMEM_P2>>>(
        ch, cl, wkvt, nullptr, kv, nullptr, nullptr, nullptr, nullptr, nullptr,
        DIM, DIM, DIM, 2 * DIM, 0, 0, 0, 1.0f);

    /* 5: LN(q)->fp16, LN(k)->fp16, v->v^T fp16 */
    prep_attn<<<dim3(ROWS, 3), 256>>>(q, kv, ln_g, ln_b, qh, kh, vt);

    /* 6: expS = exp(scale * q @ k^T - 11) -> fp16 + row sums (softmax fused) */
    gemm_hilo<__half,64,1,2,false><<<dim3(SEQ / BN, SEQ / BM, BATCH), NT, SMEM_A>>>(
        qh, nullptr, kh, nullptr, nullptr, nullptr, nullptr, ph, rs, nullptr,
        DIM, DIM, DIM, SEQ,
        (long long)SEQ * DIM, (long long)SEQ * DIM, (long long)SEQ * SEQ, ATTN_SCALE);

    /* 7: O = (expS @ v) / Z (normalized in epilogue, split bf16 out) */
    gemm_hilo<__half,64,1,3,false><<<dim3(DIM / BN, SEQ / BM, BATCH), NT, SMEM_A>>>(
        ph, nullptr, vt, nullptr, nullptr, oh, ol, nullptr, rs, nullptr,
        SEQ, SEQ, SEQ, DIM,
        (long long)SEQ * SEQ, (long long)DIM * SEQ, (long long)SEQ * DIM, 1.0f);

    /* 8: out = O @ Wo + bo (bf16x3, exact path) */
    gemm_hilo<bf16,32,3,0,true><<<dim3(DIM / BN, ROWS / BM, 1), NT, SMEM_P3>>>(
        oh, ol, woth, wotl, out, nullptr, nullptr, nullptr, nullptr, bo,
        DIM, DIM, DIM, DIM, 0, 0, 0, 1.0f);
}

// round 12
// speedup vs baseline: 1.6953x; 1.0381x over previous
#include <cuda_runtime.h>
#include <cuda_bf16.h>
#include <cuda_fp16.h>
#include <mma.h>
#include <cstdint>

using namespace nvcuda;
typedef __nv_bfloat16 bf16;

#define BATCH 4
#define SEQ   4096
#define DIM   512
#define ROWS  16384
#define ATTN_SCALE 0.125f
#define EXP_SHIFT 11.0f
#define LN_EPS 1e-5f

/* ---------------- scratch (no allocations allowed) ---------------- */
__device__ __align__(256) float g_q [(size_t)ROWS * DIM];
__device__ __align__(256) float g_kv[(size_t)ROWS * 2 * DIM];
__device__ __align__(256) float g_rs[(size_t)BATCH * SEQ];    /* softmax row sums */

__device__ __align__(256) __half g_xh [(size_t)ROWS * DIM];
__device__ __align__(256) __half g_xl [(size_t)ROWS * DIM];
__device__ __align__(256) __half g_ch [(size_t)ROWS * DIM];
__device__ __align__(256) __half g_cl [(size_t)ROWS * DIM];
__device__ __align__(256) __half g_wqt [DIM * DIM];
__device__ __align__(256) __half g_wkvt[2 * DIM * DIM];
__device__ __align__(256) __half g_wot [DIM * DIM];
__device__ __align__(256) __half g_oh [(size_t)ROWS * DIM];   /* O hi fp16 */
__device__ __align__(256) __half g_ol [(size_t)ROWS * DIM];   /* O lo fp16 */

__device__ __align__(256) __half g_qh [(size_t)ROWS * DIM];
__device__ __align__(256) __half g_kh [(size_t)ROWS * DIM];
__device__ __align__(256) __half g_vt [(size_t)BATCH * DIM * SEQ];
__device__ __align__(256) __half g_ph [(size_t)BATCH * SEQ * SEQ]; /* exp(S-11) fp16 */

/* ---------------- cp.async helpers ---------------- */
__device__ __forceinline__ unsigned smem_u32(const void* p) {
    return (unsigned)__cvta_generic_to_shared(p);
}
#define CPA16(dst, src) \
    asm volatile("cp.async.cg.shared.global [%0], [%1], 16;\n" :: "r"(dst), "l"(src))
#define CPCOMMIT() asm volatile("cp.async.commit_group;\n" ::)
template<int N> __device__ __forceinline__ void cpwait() {
    asm volatile("cp.async.wait_group %0;\n" :: "n"(N));
}

/* ---------------- hi/lo GEMM, 3-stage pipeline ----------------
 * C[M,N] = alpha * A @ B^T, B given [N,K] row-major.
 * PASSES: 2 = (Ah+Al)Bh; 1 = Ah Bh.
 * EPI: 0 = fp32 store (+bias); 2 = exp->fp16 store + rowsum atomics;
 *      3 = divide-by-rowsum then fp16 hi/lo split store.
 * 128x128 tiles, BKT k-chunk, 256 thr, 8 warps of 64x32.
 */
#define BM 128
#define BN 128
#define NT  256

template<typename T, int BKT>
__device__ __forceinline__ void stage_tile(unsigned sm, const T* g, int ld, int tid) {
    constexpr int CPR = BKT / 8;
    constexpr int AST = BKT + 8;
    #pragma unroll
    for (int i = 0; i < (128 * CPR) / NT; i++) {
        int idx = i * NT + tid;
        int r = idx / CPR, c = (idx % CPR) * 8;
        CPA16(sm + (unsigned)(r * AST + c) * 2, g + (size_t)r * ld + c);
    }
}

template<typename T, int BKT, int PASSES, int EPI, bool BIAS>
__global__ __launch_bounds__(NT, 2) void gemm_hilo(
    const T* __restrict__ Ah, const T* __restrict__ Al,
    const T* __restrict__ Bh,
    float* __restrict__ C, __half* __restrict__ Ch, __half* __restrict__ Cl,
    __half* __restrict__ Hout, float* __restrict__ rs,
    const float* __restrict__ bias,
    int K, int lda, int ldb, int ldc,
    long long sA, long long sB, long long sC, float alpha)
{
    extern __shared__ char smem[];
    constexpr int AST = BKT + 8;
    constexpr unsigned TSZ = 128u * AST * 2u;
    constexpr unsigned NTILE = (PASSES == 2) ? 3u : 2u;
    constexpr unsigned STG = NTILE * TSZ;

    const int tid  = threadIdx.x;
    const int warp = tid >> 5;
    const int wm = warp >> 2;
    const int wn = warp & 3;
    const int m0 = blockIdx.y * BM;
    const int n0 = blockIdx.x * BN;
    const long long zb = blockIdx.z;
    const unsigned sb0 = smem_u32(smem);

    const T* gAh = Ah + zb * sA + (size_t)m0 * lda;
    const T* gAl = (PASSES >= 2) ? (Al + zb * sA + (size_t)m0 * lda) : nullptr;
    const T* gBh = Bh + zb * sB + (size_t)n0 * ldb;

    wmma::fragment<wmma::accumulator, 16, 16, 16, float> acc[4][2];
    #pragma unroll
    for (int i = 0; i < 4; i++)
        #pragma unroll
        for (int j = 0; j < 2; j++)
            wmma::fill_fragment(acc[i][j], 0.0f);

    auto stage = [&](int s, int k0) {
        unsigned sp = sb0 + (unsigned)s * STG;
        stage_tile<T, BKT>(sp, gAh + k0, lda, tid);
        stage_tile<T, BKT>(sp + (NTILE - 1u) * TSZ, gBh + k0, ldb, tid);
        if (PASSES >= 2) stage_tile<T, BKT>(sp + TSZ, gAl + k0, lda, tid);
        CPCOMMIT();
    };

    const int Cn = K / BKT;
    stage(0, 0);
    if (Cn > 1) stage(1, BKT);

    int s = 0;
    for (int i = 0; i < Cn; i++) {
        if (i + 2 < Cn) {
            int s2 = s + 2; if (s2 >= 3) s2 -= 3;
            stage(s2, (i + 2) * BKT);
            cpwait<2>();
        } else if (i + 1 < Cn) {
            cpwait<1>();
        } else {
            cpwait<0>();
        }
        __syncthreads();

        T* sAh = (T*)(smem + s * STG);
        T* sAl = (T*)(smem + s * STG + TSZ);
        T* sBh = (T*)(smem + s * STG + (NTILE - 1u) * TSZ);

        #pragma unroll
        for (int kk = 0; kk < BKT; kk += 16) {
            wmma::fragment<wmma::matrix_a, 16, 16, 16, T, wmma::row_major> a[4];
            wmma::fragment<wmma::matrix_b, 16, 16, 16, T, wmma::col_major> bh[2];
            #pragma unroll
            for (int i2 = 0; i2 < 4; i2++)
                wmma::load_matrix_sync(a[i2], sAh + (wm * 64 + i2 * 16) * AST + kk, AST);
            #pragma unroll
            for (int j = 0; j < 2; j++)
                wmma::load_matrix_sync(bh[j], sBh + (wn * 32 + j * 16) * AST + kk, AST);

            #pragma unroll
            for (int i2 = 0; i2 < 4; i2++)
                #pragma unroll
                for (int j = 0; j < 2; j++)
                    wmma::mma_sync(acc[i2][j], a[i2], bh[j], acc[i2][j]);

            if (PASSES >= 2) {
                #pragma unroll
                for (int i2 = 0; i2 < 4; i2++)
                    wmma::load_matrix_sync(a[i2], sAl + (wm * 64 + i2 * 16) * AST + kk, AST);
                #pragma unroll
                for (int i2 = 0; i2 < 4; i2++)
                    #pragma unroll
                    for (int j = 0; j < 2; j++)
                        wmma::mma_sync(acc[i2][j], a[i2], bh[j], acc[i2][j]);
            }
        }
        __syncthreads();
        s = (s + 1 == 3) ? 0 : s + 1;
    }

    /* ---- epilogue via smem (128 x 132 fp32) ---- */
    float* cs = (float*)smem;
    #pragma unroll
    for (int i = 0; i < 4; i++)
        #pragma unroll
        for (int j = 0; j < 2; j++) {
            #pragma unroll
            for (int t = 0; t < acc[i][j].num_elements; t++)
                acc[i][j].x[t] *= alpha;
            wmma::store_matrix_sync(cs + (wm * 64 + i * 16) * 132 + wn * 32 + j * 16,
                                    acc[i][j], 132, wmma::mem_row_major);
        }
    __syncthreads();

    #pragma unroll
    for (int it = 0; it < 16; it++) {
        int idx = it * NT + tid;
        int r = idx >> 5, c4 = (idx & 31) * 4;   /* whole warp shares row r */
        float4 v = *(float4*)(cs + r * 132 + c4);

        if (EPI == 2) {
            float e0 = __expf(v.x - EXP_SHIFT);
            float e1 = __expf(v.y - EXP_SHIFT);
            float e2 = __expf(v.z - EXP_SHIFT);
            float e3 = __expf(v.w - EXP_SHIFT);
            size_t base = (size_t)zb * sC + (size_t)(m0 + r) * ldc + n0 + c4;
            __half2 t;
            t.x = __float2half(e0); t.y = __float2half(e1);
            *(__half2*)(Hout + base) = t;
            t.x = __float2half(e2); t.y = __float2half(e3);
            *(__half2*)(Hout + base + 2) = t;
            float s4 = (e0 + e1) + (e2 + e3);
            #pragma unroll
            for (int o = 16; o > 0; o >>= 1)
                s4 += __shfl_xor_sync(0xffffffffu, s4, o);
            if ((tid & 31) == 0)
                atomicAdd(&rs[(size_t)zb * SEQ + m0 + r], s4);
        } else if (EPI == 3) {
            float zi = __fdividef(1.0f, rs[(size_t)zb * SEQ + m0 + r]);
            v.x *= zi; v.y *= zi; v.z *= zi; v.w *= zi;
            size_t base = (size_t)zb * sC + (size_t)(m0 + r) * ldc + n0 + c4;
            __half h0 = __float2half(v.x), h1 = __float2half(v.y);
            __half h2 = __float2half(v.z), h3 = __float2half(v.w);
            __half2 t;
            t.x = h0; t.y = h1; *(__half2*)(Ch + base) = t;
            t.x = h2; t.y = h3; *(__half2*)(Ch + base + 2) = t;
            t.x = __float2half(v.x - __half2float(h0));
            t.y = __float2half(v.y - __half2float(h1));
            *(__half2*)(Cl + base) = t;
            t.x = __float2half(v.z - __half2float(h2));
            t.y = __float2half(v.w - __half2float(h3));
            *(__half2*)(Cl + base + 2) = t;
        } else {
            if (BIAS) {
                v.x += bias[n0 + c4 + 0];
                v.y += bias[n0 + c4 + 1];
                v.z += bias[n0 + c4 + 2];
                v.w += bias[n0 + c4 + 3];
            }
            size_t base = (size_t)zb * sC + (size_t)(m0 + r) * ldc + n0 + c4;
            *(float4*)(C + base) = v;
        }
    }
}

/* ---------------- zero the rowsum accumulator ---------------- */
__global__ __launch_bounds__(256) void zero_rs(float* __restrict__ rs)
{
    rs[blockIdx.x * 256 + threadIdx.x] = 0.0f;
}

/* ---------------- fused input split: x/ctx -> fp16 hi/lo ------------- */
__global__ __launch_bounds__(256) void split_inputs(
    const float* __restrict__ x, const float* __restrict__ ctx,
    __half* __restrict__ xh, __half* __restrict__ xl,
    __half* __restrict__ ch, __half* __restrict__ cl)
{
    const float* in = blockIdx.y ? ctx : x;
    __half* h = blockIdx.y ? ch : xh;
    __half* l = blockIdx.y ? cl : xl;
    size_t i = (size_t)blockIdx.x * 256 + threadIdx.x;
    float4 v = ((const float4*)in)[i];
    __half h0 = __float2half(v.x), h1 = __float2half(v.y);
    __half h2 = __float2half(v.z), h3 = __float2half(v.w);
    __half2 t;
    t.x = h0; t.y = h1; *(__half2*)(h + i * 4) = t;
    t.x = h2; t.y = h3; *(__half2*)(h + i * 4 + 2) = t;
    t.x = __float2half(v.x - __half2float(h0));
    t.y = __float2half(v.y - __half2float(h1));
    *(__half2*)(l + i * 4) = t;
    t.x = __float2half(v.z - __half2float(h2));
    t.y = __float2half(v.w - __half2float(h3));
    *(__half2*)(l + i * 4 + 2) = t;
}

/* ---------------- weights: all -> W^T fp16 single ---------------- */
__global__ __launch_bounds__(256) void wsplit_all(
    const float* __restrict__ Wq, const float* __restrict__ Wkv, const float* __restrict__ Wo,
    __half* __restrict__ wqt, __half* __restrict__ wkvt, __half* __restrict__ wot)
{
    __shared__ float t[32][33];
    int bx = blockIdx.x;
    const float* W; __half* th; int N, tidx;
    if (bx < 256)      { W = Wq;  th = wqt;  N = DIM;     tidx = bx;       }
    else if (bx < 768) { W = Wkv; th = wkvt; N = 2 * DIM; tidx = bx - 256; }
    else               { W = Wo;  th = wot;  N = DIM;     tidx = bx - 768; }
    int nT = N / 32;
    int n0 = (tidx % nT) * 32, k0 = (tidx / nT) * 32;
    int tx = threadIdx.x & 31, ty = threadIdx.x >> 5;
    #pragma unroll
    for (int j = 0; j < 4; j++) {
        int r = ty + j * 8;
        t[r][tx] = W[(size_t)(k0 + r) * N + n0 + tx];
    }
    __syncthreads();
    #pragma unroll
    for (int j = 0; j < 4; j++) {
        int r = ty + j * 8;
        th[(size_t)(n0 + r) * DIM + k0 + tx] = __float2half(t[tx][r]);
    }
}

/* ---------------- fused attention prep ---------------- */
__global__ __launch_bounds__(256) void prep_attn(
    const float* __restrict__ q, const float* __restrict__ kv,
    const float* __restrict__ g, const float* __restrict__ b,
    __half* __restrict__ qh, __half* __restrict__ kh, __half* __restrict__ vt)
{
    const int mode = blockIdx.y;
    int tid = threadIdx.x;

    if (mode == 2) {                     /* v transpose, fp16 single */
        if (blockIdx.x >= 8192) return;
        __shared__ float t[32][33];
        int bx = blockIdx.x;
        int bb = bx >> 11;
        int rem = bx & 2047;
        int d0 = (rem >> 7) * 32;
        int m0 = (rem & 127) * 32;
        int tx = tid & 31, ty = tid >> 5;
        const float* src = kv + ((size_t)bb * SEQ) * (2 * DIM) + DIM;
        #pragma unroll
        for (int j = 0; j < 4; j++) {
            int r = ty + j * 8;
            t[r][tx] = src[(size_t)(m0 + r) * (2 * DIM) + d0 + tx];
        }
        __syncthreads();
        #pragma unroll
        for (int j = 0; j < 4; j++) {
            int r = ty + j * 8;
            vt[((size_t)bb * DIM + d0 + r) * SEQ + m0 + tx] = __float2half(t[tx][r]);
        }
        return;
    }

    __shared__ float red[16];
    const float* row = (mode == 0) ? q + (size_t)blockIdx.x * DIM
                                   : kv + (size_t)blockIdx.x * (2 * DIM);
    float x0 = row[tid];
    float x1 = row[tid + 256];
    float s  = x0 + x1;
    float sq = x0 * x0 + x1 * x1;
    #pragma unroll
    for (int o = 16; o > 0; o >>= 1) {
        s  += __shfl_xor_sync(0xffffffffu, s,  o);
        sq += __shfl_xor_sync(0xffffffffu, sq, o);
    }
    if ((tid & 31) == 0) { red[tid >> 5] = s; red[8 + (tid >> 5)] = sq; }
    __syncthreads();
    if (tid < 32) {
        float vs = (tid < 8) ? red[tid] : 0.0f;
        float vq = (tid < 8) ? red[8 + tid] : 0.0f;
        #pragma unroll
        for (int o = 4; o > 0; o >>= 1) {
            vs += __shfl_xor_sync(0xffffffffu, vs, o);
            vq += __shfl_xor_sync(0xffffffffu, vq, o);
        }
        if (tid == 0) { red[0] = vs; red[1] = vq; }
    }
    __syncthreads();
    float mean = red[0] * (1.0f / 512.0f);
    float var  = red[1] * (1.0f / 512.0f) - mean * mean;
    float rstd = rsqrtf(var + LN_EPS);
    float y0 = (x0 - mean) * rstd * g[tid]       + b[tid];
    float y1 = (x1 - mean) * rstd * g[tid + 256] + b[tid + 256];
    __half* hr = (mode == 0) ? qh + (size_t)blockIdx.x * DIM
                             : kh + (size_t)blockIdx.x * DIM;
    hr[tid]       = __float2half(y0);
    hr[tid + 256] = __float2half(y1);
}

/* ---------------- launcher ---------------- */
#define SMEM_P2 92160u     /* fp16x2 proj: 3 stages x 3 tiles (BK=32)  */
#define SMEM_A 110592u     /* attn: 3 stages x 2 tiles (BK=64)         */

extern "C" void kernel_launch(void* const* d_in, const int* in_sizes, int n_in,
                              void* d_out, int out_size)
{
    const float* x    = (const float*)d_in[0];
    const float* ctx  = (const float*)d_in[1];
    const float* Wq   = (const float*)d_in[2];
    const float* Wkv  = (const float*)d_in[3];
    const float* Wo   = (const float*)d_in[4];
    const float* bo   = (const float*)d_in[5];
    const float* ln_g = (const float*)d_in[6];
    const float* ln_b = (const float*)d_in[7];
    float* out = (float*)d_out;

    float *q, *kv, *rs;
    __half *xh, *xl, *ch, *cl, *wqt, *wkvt, *wot, *oh, *ol, *qh, *kh, *vt, *ph;
    cudaGetSymbolAddress((void**)&q,    g_q);
    cudaGetSymbolAddress((void**)&kv,   g_kv);
    cudaGetSymbolAddress((void**)&rs,   g_rs);
    cudaGetSymbolAddress((void**)&xh,   g_xh);    cudaGetSymbolAddress((void**)&xl,   g_xl);
    cudaGetSymbolAddress((void**)&ch,   g_ch);    cudaGetSymbolAddress((void**)&cl,   g_cl);
    cudaGetSymbolAddress((void**)&wqt,  g_wqt);   cudaGetSymbolAddress((void**)&wkvt, g_wkvt);
    cudaGetSymbolAddress((void**)&wot,  g_wot);
    cudaGetSymbolAddress((void**)&oh,   g_oh);    cudaGetSymbolAddress((void**)&ol,   g_ol);
    cudaGetSymbolAddress((void**)&qh,   g_qh);    cudaGetSymbolAddress((void**)&kh,   g_kh);
    cudaGetSymbolAddress((void**)&vt,   g_vt);    cudaGetSymbolAddress((void**)&ph,   g_ph);

    cudaFuncSetAttribute(gemm_hilo<__half,32, 2, 0, false>,
                         cudaFuncAttributeMaxDynamicSharedMemorySize, SMEM_P2);
    cudaFuncSetAttribute(gemm_hilo<__half,32, 2, 0, true>,
                         cudaFuncAttributeMaxDynamicSharedMemorySize, SMEM_P2);
    cudaFuncSetAttribute(gemm_hilo<__half,64, 1, 2, false>,
                         cudaFuncAttributeMaxDynamicSharedMemorySize, SMEM_A);
    cudaFuncSetAttribute(gemm_hilo<__half,64, 1, 3, false>,
                         cudaFuncAttributeMaxDynamicSharedMemorySize, SMEM_A);

    /* 0: split inputs to fp16 hi/lo */
    split_inputs<<<dim3(ROWS * DIM / 4 / 256, 2), 256>>>(x, ctx, xh, xl, ch, cl);
    /* 1: weights -> fp16 transpose */
    wsplit_all<<<1024, 256>>>(Wq, Wkv, Wo, wqt, wkvt, wot);
    /* 2: zero softmax row sums */
    zero_rs<<<(BATCH * SEQ) / 256, 256>>>(rs);

    /* 3: q = x @ Wq (fp16x2) */
    gemm_hilo<__half,32,2,0,false><<<dim3(DIM / BN, ROWS / BM, 1), NT, SMEM_P2>>>(
        xh, xl, wqt, q, nullptr, nullptr, nullptr, nullptr, nullptr,
        DIM, DIM, DIM, DIM, 0, 0, 0, 1.0f);

    /* 4: kv = ctx @ Wkv (fp16x2) */
    gemm_hilo<__half,32,2,0,false><<<dim3(2 * DIM / BN, ROWS / BM, 1), NT, SMEM_P2>>>(
        ch, cl, wkvt, kv, nullptr, nullptr, nullptr, nullptr, nullptr,
        DIM, DIM, DIM, 2 * DIM, 0, 0, 0, 1.0f);

    /* 5: LN(q)->fp16, LN(k)->fp16, v->v^T fp16 */
    prep_attn<<<dim3(ROWS, 3), 256>>>(q, kv, ln_g, ln_b, qh, kh, vt);

    /* 6: expS = exp(scale * q @ k^T - 11) -> fp16 + row sums */
    gemm_hilo<__half,64,1,2,false><<<dim3(SEQ / BN, SEQ / BM, BATCH), NT, SMEM_A>>>(
        qh, nullptr, kh, nullptr, nullptr, nullptr, ph, rs, nullptr,
        DIM, DIM, DIM, SEQ,
        (long long)SEQ * DIM, (long long)SEQ * DIM, (long long)SEQ * SEQ, ATTN_SCALE);

    /* 7: O = (expS @ v) / Z -> fp16 hi/lo */
    gemm_hilo<__half,64,1,3,false><<<dim3(DIM / BN, SEQ / BM, BATCH), NT, SMEM_A>>>(
        ph, nullptr, vt, nullptr, oh, ol, nullptr, rs, nullptr,
        SEQ, SEQ, SEQ, DIM,
        (long long)SEQ * SEQ, (long long)DIM * SEQ, (long long)SEQ * DIM, 1.0f);

    /* 8: out = O @ Wo + bo (fp16x2: O split, Wo single) */
    gemm_hilo<__half,32,2,0,true><<<dim3(DIM / BN, ROWS / BM, 1), NT, SMEM_P2>>>(
        oh, ol, wot, out, nullptr, nullptr, nullptr, nullptr, bo,
        DIM, DIM, DIM, DIM, 0, 0, 0, 1.0f);
}

// round 13
// speedup vs baseline: 1.7119x; 1.0098x over previous
#include <cuda_runtime.h>
#include <cuda_bf16.h>
#include <cuda_fp16.h>
#include <mma.h>
#include <cstdint>

using namespace nvcuda;
typedef __nv_bfloat16 bf16;

#define BATCH 4
#define SEQ   4096
#define DIM   512
#define ROWS  16384
#define ATTN_SCALE 0.125f
#define EXP_SHIFT 11.0f
#define LN_EPS 1e-5f

/* ---------------- scratch (no allocations allowed) ---------------- */
__device__ __align__(256) float g_q [(size_t)ROWS * DIM];
__device__ __align__(256) float g_kv[(size_t)ROWS * 2 * DIM];
__device__ __align__(256) float g_rs[(size_t)BATCH * SEQ];    /* softmax row sums */

__device__ __align__(256) __half g_xh [(size_t)ROWS * DIM];
__device__ __align__(256) __half g_xl [(size_t)ROWS * DIM];
__device__ __align__(256) __half g_ch [(size_t)ROWS * DIM];
__device__ __align__(256) __half g_cl [(size_t)ROWS * DIM];
__device__ __align__(256) __half g_wqt [DIM * DIM];
__device__ __align__(256) __half g_wkvt[2 * DIM * DIM];
__device__ __align__(256) __half g_wot [DIM * DIM];
__device__ __align__(256) __half g_oh [(size_t)ROWS * DIM];   /* O hi fp16 */
__device__ __align__(256) __half g_ol [(size_t)ROWS * DIM];   /* O lo fp16 */

__device__ __align__(256) __half g_qh [(size_t)ROWS * DIM];
__device__ __align__(256) __half g_kh [(size_t)ROWS * DIM];
__device__ __align__(256) __half g_vt [(size_t)BATCH * DIM * SEQ];
__device__ __align__(256) __half g_ph [(size_t)BATCH * SEQ * SEQ]; /* exp(S-11) fp16 */

/* ---------------- cp.async helpers ---------------- */
__device__ __forceinline__ unsigned smem_u32(const void* p) {
    return (unsigned)__cvta_generic_to_shared(p);
}
#define CPA16(dst, src) \
    asm volatile("cp.async.cg.shared.global [%0], [%1], 16;\n" :: "r"(dst), "l"(src))
#define CPCOMMIT() asm volatile("cp.async.commit_group;\n" ::)
template<int N> __device__ __forceinline__ void cpwait() {
    asm volatile("cp.async.wait_group %0;\n" :: "n"(N));
}

/* ---------------- hi/lo GEMM, 3-stage pipeline ----------------
 * C[M,N] = alpha * A @ B^T, B given [N,K] row-major.
 * PASSES: 2 = (Ah+Al)Bh; 1 = Ah Bh.
 * EPI: 0 = fp32 direct store (no bias) / smem+bias if BIAS;
 *      2 = exp->fp16 store + rowsum atomics;
 *      3 = divide-by-rowsum then fp16 hi/lo split store.
 * 128x128 tiles, BKT k-chunk, 256 thr, 8 warps of 64x32.
 */
#define BM 128
#define BN 128
#define NT  256

template<typename T, int BKT>
__device__ __forceinline__ void stage_tile(unsigned sm, const T* g, int ld, int tid) {
    constexpr int CPR = BKT / 8;
    constexpr int AST = BKT + 8;
    #pragma unroll
    for (int i = 0; i < (128 * CPR) / NT; i++) {
        int idx = i * NT + tid;
        int r = idx / CPR, c = (idx % CPR) * 8;
        CPA16(sm + (unsigned)(r * AST + c) * 2, g + (size_t)r * ld + c);
    }
}

template<typename T, int BKT, int PASSES, int EPI, bool BIAS>
__global__ __launch_bounds__(NT, 2) void gemm_hilo(
    const T* __restrict__ Ah, const T* __restrict__ Al,
    const T* __restrict__ Bh,
    float* __restrict__ C, __half* __restrict__ Ch, __half* __restrict__ Cl,
    __half* __restrict__ Hout, float* __restrict__ rs,
    const float* __restrict__ bias,
    int K, int lda, int ldb, int ldc,
    long long sA, long long sB, long long sC, float alpha)
{
    extern __shared__ char smem[];
    constexpr int AST = BKT + 8;
    constexpr unsigned TSZ = 128u * AST * 2u;
    constexpr unsigned NTILE = (PASSES == 2) ? 3u : 2u;
    constexpr unsigned STG = NTILE * TSZ;

    const int tid  = threadIdx.x;
    const int warp = tid >> 5;
    const int wm = warp >> 2;
    const int wn = warp & 3;
    const int m0 = blockIdx.y * BM;
    const int n0 = blockIdx.x * BN;
    const long long zb = blockIdx.z;
    const unsigned sb0 = smem_u32(smem);

    const T* gAh = Ah + zb * sA + (size_t)m0 * lda;
    const T* gAl = (PASSES >= 2) ? (Al + zb * sA + (size_t)m0 * lda) : nullptr;
    const T* gBh = Bh + zb * sB + (size_t)n0 * ldb;

    wmma::fragment<wmma::accumulator, 16, 16, 16, float> acc[4][2];
    #pragma unroll
    for (int i = 0; i < 4; i++)
        #pragma unroll
        for (int j = 0; j < 2; j++)
            wmma::fill_fragment(acc[i][j], 0.0f);

    auto stage = [&](int s, int k0) {
        unsigned sp = sb0 + (unsigned)s * STG;
        stage_tile<T, BKT>(sp, gAh + k0, lda, tid);
        stage_tile<T, BKT>(sp + (NTILE - 1u) * TSZ, gBh + k0, ldb, tid);
        if (PASSES >= 2) stage_tile<T, BKT>(sp + TSZ, gAl + k0, lda, tid);
        CPCOMMIT();
    };

    const int Cn = K / BKT;
    stage(0, 0);
    if (Cn > 1) stage(1, BKT);

    int s = 0;
    for (int i = 0; i < Cn; i++) {
        if (i + 2 < Cn) {
            int s2 = s + 2; if (s2 >= 3) s2 -= 3;
            stage(s2, (i + 2) * BKT);
            cpwait<2>();
        } else if (i + 1 < Cn) {
            cpwait<1>();
        } else {
            cpwait<0>();
        }
        __syncthreads();

        T* sAh = (T*)(smem + s * STG);
        T* sAl = (T*)(smem + s * STG + TSZ);
        T* sBh = (T*)(smem + s * STG + (NTILE - 1u) * TSZ);

        #pragma unroll
        for (int kk = 0; kk < BKT; kk += 16) {
            wmma::fragment<wmma::matrix_a, 16, 16, 16, T, wmma::row_major> a[4];
            wmma::fragment<wmma::matrix_b, 16, 16, 16, T, wmma::col_major> bh[2];
            #pragma unroll
            for (int i2 = 0; i2 < 4; i2++)
                wmma::load_matrix_sync(a[i2], sAh + (wm * 64 + i2 * 16) * AST + kk, AST);
            #pragma unroll
            for (int j = 0; j < 2; j++)
                wmma::load_matrix_sync(bh[j], sBh + (wn * 32 + j * 16) * AST + kk, AST);

            #pragma unroll
            for (int i2 = 0; i2 < 4; i2++)
                #pragma unroll
                for (int j = 0; j < 2; j++)
                    wmma::mma_sync(acc[i2][j], a[i2], bh[j], acc[i2][j]);

            if (PASSES >= 2) {
                #pragma unroll
                for (int i2 = 0; i2 < 4; i2++)
                    wmma::load_matrix_sync(a[i2], sAl + (wm * 64 + i2 * 16) * AST + kk, AST);
                #pragma unroll
                for (int i2 = 0; i2 < 4; i2++)
                    #pragma unroll
                    for (int j = 0; j < 2; j++)
                        wmma::mma_sync(acc[i2][j], a[i2], bh[j], acc[i2][j]);
            }
        }
        __syncthreads();
        s = (s + 1 == 3) ? 0 : s + 1;
    }

    if (EPI == 0 && !BIAS) {
        /* direct global store: no smem roundtrip, no extra syncs */
        #pragma unroll
        for (int i = 0; i < 4; i++)
            #pragma unroll
            for (int j = 0; j < 2; j++) {
                if (alpha != 1.0f)
                    #pragma unroll
                    for (int t = 0; t < acc[i][j].num_elements; t++)
                        acc[i][j].x[t] *= alpha;
                wmma::store_matrix_sync(
                    C + (size_t)zb * sC + (size_t)(m0 + wm * 64 + i * 16) * ldc
                      + n0 + wn * 32 + j * 16,
                    acc[i][j], ldc, wmma::mem_row_major);
            }
        return;
    }

    /* ---- epilogue via smem (128 x 132 fp32) ---- */
    float* cs = (float*)smem;
    #pragma unroll
    for (int i = 0; i < 4; i++)
        #pragma unroll
        for (int j = 0; j < 2; j++) {
            #pragma unroll
            for (int t = 0; t < acc[i][j].num_elements; t++)
                acc[i][j].x[t] *= alpha;
            wmma::store_matrix_sync(cs + (wm * 64 + i * 16) * 132 + wn * 32 + j * 16,
                                    acc[i][j], 132, wmma::mem_row_major);
        }
    __syncthreads();

    #pragma unroll
    for (int it = 0; it < 16; it++) {
        int idx = it * NT + tid;
        int r = idx >> 5, c4 = (idx & 31) * 4;   /* whole warp shares row r */
        float4 v = *(float4*)(cs + r * 132 + c4);

        if (EPI == 2) {
            float e0 = __expf(v.x - EXP_SHIFT);
            float e1 = __expf(v.y - EXP_SHIFT);
            float e2 = __expf(v.z - EXP_SHIFT);
            float e3 = __expf(v.w - EXP_SHIFT);
            size_t base = (size_t)zb * sC + (size_t)(m0 + r) * ldc + n0 + c4;
            __half2 t;
            t.x = __float2half(e0); t.y = __float2half(e1);
            *(__half2*)(Hout + base) = t;
            t.x = __float2half(e2); t.y = __float2half(e3);
            *(__half2*)(Hout + base + 2) = t;
            float s4 = (e0 + e1) + (e2 + e3);
            #pragma unroll
            for (int o = 16; o > 0; o >>= 1)
                s4 += __shfl_xor_sync(0xffffffffu, s4, o);
            if ((tid & 31) == 0)
                atomicAdd(&rs[(size_t)zb * SEQ + m0 + r], s4);
        } else if (EPI == 3) {
            float zi = __fdividef(1.0f, rs[(size_t)zb * SEQ + m0 + r]);
            v.x *= zi; v.y *= zi; v.z *= zi; v.w *= zi;
            size_t base = (size_t)zb * sC + (size_t)(m0 + r) * ldc + n0 + c4;
            __half h0 = __float2half(v.x), h1 = __float2half(v.y);
            __half h2 = __float2half(v.z), h3 = __float2half(v.w);
            __half2 t;
            t.x = h0; t.y = h1; *(__half2*)(Ch + base) = t;
            t.x = h2; t.y = h3; *(__half2*)(Ch + base + 2) = t;
            t.x = __float2half(v.x - __half2float(h0));
            t.y = __float2half(v.y - __half2float(h1));
            *(__half2*)(Cl + base) = t;
            t.x = __float2half(v.z - __half2float(h2));
            t.y = __float2half(v.w - __half2float(h3));
            *(__half2*)(Cl + base + 2) = t;
        } else {
            if (BIAS) {
                v.x += bias[n0 + c4 + 0];
                v.y += bias[n0 + c4 + 1];
                v.z += bias[n0 + c4 + 2];
                v.w += bias[n0 + c4 + 3];
            }
            size_t base = (size_t)zb * sC + (size_t)(m0 + r) * ldc + n0 + c4;
            *(float4*)(C + base) = v;
        }
    }
}

/* ---------------- fused input split: x/ctx -> fp16 hi/lo ------------- */
__global__ __launch_bounds__(256) void split_inputs(
    const float* __restrict__ x, const float* __restrict__ ctx,
    __half* __restrict__ xh, __half* __restrict__ xl,
    __half* __restrict__ ch, __half* __restrict__ cl)
{
    const float* in = blockIdx.y ? ctx : x;
    __half* h = blockIdx.y ? ch : xh;
    __half* l = blockIdx.y ? cl : xl;
    size_t i = (size_t)blockIdx.x * 256 + threadIdx.x;
    float4 v = ((const float4*)in)[i];
    __half h0 = __float2half(v.x), h1 = __float2half(v.y);
    __half h2 = __float2half(v.z), h3 = __float2half(v.w);
    __half2 t;
    t.x = h0; t.y = h1; *(__half2*)(h + i * 4) = t;
    t.x = h2; t.y = h3; *(__half2*)(h + i * 4 + 2) = t;
    t.x = __float2half(v.x - __half2float(h0));
    t.y = __float2half(v.y - __half2float(h1));
    *(__half2*)(l + i * 4) = t;
    t.x = __float2half(v.z - __half2float(h2));
    t.y = __float2half(v.w - __half2float(h3));
    *(__half2*)(l + i * 4 + 2) = t;
}

/* ---------------- weights -> W^T fp16 single; tail blocks zero rs -------- */
__global__ __launch_bounds__(256) void wsplit_all(
    const float* __restrict__ Wq, const float* __restrict__ Wkv, const float* __restrict__ Wo,
    __half* __restrict__ wqt, __half* __restrict__ wkvt, __half* __restrict__ wot,
    float* __restrict__ rs)
{
    int bx = blockIdx.x;
    if (bx >= 1024) {                  /* 64 tail blocks zero the rowsums */
        rs[(bx - 1024) * 256 + threadIdx.x] = 0.0f;
        return;
    }
    __shared__ float t[32][33];
    const float* W; __half* th; int N, tidx;
    if (bx < 256)      { W = Wq;  th = wqt;  N = DIM;     tidx = bx;       }
    else if (bx < 768) { W = Wkv; th = wkvt; N = 2 * DIM; tidx = bx - 256; }
    else               { W = Wo;  th = wot;  N = DIM;     tidx = bx - 768; }
    int nT = N / 32;
    int n0 = (tidx % nT) * 32, k0 = (tidx / nT) * 32;
    int tx = threadIdx.x & 31, ty = threadIdx.x >> 5;
    #pragma unroll
    for (int j = 0; j < 4; j++) {
        int r = ty + j * 8;
        t[r][tx] = W[(size_t)(k0 + r) * N + n0 + tx];
    }
    __syncthreads();
    #pragma unroll
    for (int j = 0; j < 4; j++) {
        int r = ty + j * 8;
        th[(size_t)(n0 + r) * DIM + k0 + tx] = __float2half(t[tx][r]);
    }
}

/* ---------------- fused attention prep ---------------- */
__global__ __launch_bounds__(256) void prep_attn(
    const float* __restrict__ q, const float* __restrict__ kv,
    const float* __restrict__ g, const float* __restrict__ b,
    __half* __restrict__ qh, __half* __restrict__ kh, __half* __restrict__ vt)
{
    const int mode = blockIdx.y;
    int tid = threadIdx.x;

    if (mode == 2) {                     /* v transpose, fp16 single */
        if (blockIdx.x >= 8192) return;
        __shared__ float t[32][33];
        int bx = blockIdx.x;
        int bb = bx >> 11;
        int rem = bx & 2047;
        int d0 = (rem >> 7) * 32;
        int m0 = (rem & 127) * 32;
        int tx = tid & 31, ty = tid >> 5;
        const float* src = kv + ((size_t)bb * SEQ) * (2 * DIM) + DIM;
        #pragma unroll
        for (int j = 0; j < 4; j++) {
            int r = ty + j * 8;
            t[r][tx] = src[(size_t)(m0 + r) * (2 * DIM) + d0 + tx];
        }
        __syncthreads();
        #pragma unroll
        for (int j = 0; j < 4; j++) {
            int r = ty + j * 8;
            vt[((size_t)bb * DIM + d0 + r) * SEQ + m0 + tx] = __float2half(t[tx][r]);
        }
        return;
    }

    __shared__ float red[16];
    const float* row = (mode == 0) ? q + (size_t)blockIdx.x * DIM
                                   : kv + (size_t)blockIdx.x * (2 * DIM);
    float x0 = row[tid];
    float x1 = row[tid + 256];
    float s  = x0 + x1;
    float sq = x0 * x0 + x1 * x1;
    #pragma unroll
    for (int o = 16; o > 0; o >>= 1) {
        s  += __shfl_xor_sync(0xffffffffu, s,  o);
        sq += __shfl_xor_sync(0xffffffffu, sq, o);
    }
    if ((tid & 31) == 0) { red[tid >> 5] = s; red[8 + (tid >> 5)] = sq; }
    __syncthreads();
    if (tid < 32) {
        float vs = (tid < 8) ? red[tid] : 0.0f;
        float vq = (tid < 8) ? red[8 + tid] : 0.0f;
        #pragma unroll
        for (int o = 4; o > 0; o >>= 1) {
            vs += __shfl_xor_sync(0xffffffffu, vs, o);
            vq += __shfl_xor_sync(0xffffffffu, vq, o);
        }
        if (tid == 0) { red[0] = vs; red[1] = vq; }
    }
    __syncthreads();
    float mean = red[0] * (1.0f / 512.0f);
    float var  = red[1] * (1.0f / 512.0f) - mean * mean;
    float rstd = rsqrtf(var + LN_EPS);
    float y0 = (x0 - mean) * rstd * g[tid]       + b[tid];
    float y1 = (x1 - mean) * rstd * g[tid + 256] + b[tid + 256];
    __half* hr = (mode == 0) ? qh + (size_t)blockIdx.x * DIM
                             : kh + (size_t)blockIdx.x * DIM;
    hr[tid]       = __float2half(y0);
    hr[tid + 256] = __float2half(y1);
}

/* ---------------- launcher ---------------- */
#define SMEM_P2 92160u     /* fp16x2 proj: 3 stages x 3 tiles (BK=32)  */
#define SMEM_A 110592u     /* attn: 3 stages x 2 tiles (BK=64)         */

extern "C" void kernel_launch(void* const* d_in, const int* in_sizes, int n_in,
                              void* d_out, int out_size)
{
    const float* x    = (const float*)d_in[0];
    const float* ctx  = (const float*)d_in[1];
    const float* Wq   = (const float*)d_in[2];
    const float* Wkv  = (const float*)d_in[3];
    const float* Wo   = (const float*)d_in[4];
    const float* bo   = (const float*)d_in[5];
    const float* ln_g = (const float*)d_in[6];
    const float* ln_b = (const float*)d_in[7];
    float* out = (float*)d_out;

    float *q, *kv, *rs;
    __half *xh, *xl, *ch, *cl, *wqt, *wkvt, *wot, *oh, *ol, *qh, *kh, *vt, *ph;
    cudaGetSymbolAddress((void**)&q,    g_q);
    cudaGetSymbolAddress((void**)&kv,   g_kv);
    cudaGetSymbolAddress((void**)&rs,   g_rs);
    cudaGetSymbolAddress((void**)&xh,   g_xh);    cudaGetSymbolAddress((void**)&xl,   g_xl);
    cudaGetSymbolAddress((void**)&ch,   g_ch);    cudaGetSymbolAddress((void**)&cl,   g_cl);
    cudaGetSymbolAddress((void**)&wqt,  g_wqt);   cudaGetSymbolAddress((void**)&wkvt, g_wkvt);
    cudaGetSymbolAddress((void**)&wot,  g_wot);
    cudaGetSymbolAddress((void**)&oh,   g_oh);    cudaGetSymbolAddress((void**)&ol,   g_ol);
    cudaGetSymbolAddress((void**)&qh,   g_qh);    cudaGetSymbolAddress((void**)&kh,   g_kh);
    cudaGetSymbolAddress((void**)&vt,   g_vt);    cudaGetSymbolAddress((void**)&ph,   g_ph);

    cudaFuncSetAttribute(gemm_hilo<__half,32, 2, 0, false>,
                         cudaFuncAttributeMaxDynamicSharedMemorySize, SMEM_P2);
    cudaFuncSetAttribute(gemm_hilo<__half,32, 2, 0, true>,
                         cudaFuncAttributeMaxDynamicSharedMemorySize, SMEM_P2);
    cudaFuncSetAttribute(gemm_hilo<__half,64, 1, 2, false>,
                         cudaFuncAttributeMaxDynamicSharedMemorySize, SMEM_A);
    cudaFuncSetAttribute(gemm_hilo<__half,64, 1, 3, false>,
                         cudaFuncAttributeMaxDynamicSharedMemorySize, SMEM_A);

    /* 0: split inputs to fp16 hi/lo */
    split_inputs<<<dim3(ROWS * DIM / 4 / 256, 2), 256>>>(x, ctx, xh, xl, ch, cl);
    /* 1: weights -> fp16 transpose (+ zero rowsums in tail blocks) */
    wsplit_all<<<1088, 256>>>(Wq, Wkv, Wo, wqt, wkvt, wot, rs);

    /* 2: q = x @ Wq (fp16x2, direct-store epilogue) */
    gemm_hilo<__half,32,2,0,false><<<dim3(DIM / BN, ROWS / BM, 1), NT, SMEM_P2>>>(
        xh, xl, wqt, q, nullptr, nullptr, nullptr, nullptr, nullptr,
        DIM, DIM, DIM, DIM, 0, 0, 0, 1.0f);

    /* 3: kv = ctx @ Wkv (fp16x2, direct-store epilogue) */
    gemm_hilo<__half,32,2,0,false><<<dim3(2 * DIM / BN, ROWS / BM, 1), NT, SMEM_P2>>>(
        ch, cl, wkvt, kv, nullptr, nullptr, nullptr, nullptr, nullptr,
        DIM, DIM, DIM, 2 * DIM, 0, 0, 0, 1.0f);

    /* 4: LN(q)->fp16, LN(k)->fp16, v->v^T fp16 */
    prep_attn<<<dim3(ROWS, 3), 256>>>(q, kv, ln_g, ln_b, qh, kh, vt);

    /* 5: expS = exp(scale * q @ k^T - 11) -> fp16 + row sums */
    gemm_hilo<__half,64,1,2,false><<<dim3(SEQ / BN, SEQ / BM, BATCH), NT, SMEM_A>>>(
        qh, nullptr, kh, nullptr, nullptr, nullptr, ph, rs, nullptr,
        DIM, DIM, DIM, SEQ,
        (long long)SEQ * DIM, (long long)SEQ * DIM, (long long)SEQ * SEQ, ATTN_SCALE);

    /* 6: O = (expS @ v) / Z -> fp16 hi/lo */
    gemm_hilo<__half,64,1,3,false><<<dim3(DIM / BN, SEQ / BM, BATCH), NT, SMEM_A>>>(
        ph, nullptr, vt, nullptr, oh, ol, nullptr, rs, nullptr,
        SEQ, SEQ, SEQ, DIM,
        (long long)SEQ * SEQ, (long long)DIM * SEQ, (long long)SEQ * DIM, 1.0f);

    /* 7: out = O @ Wo + bo (fp16x2, smem epilogue for bias) */
    gemm_hilo<__half,32,2,0,true><<<dim3(DIM / BN, ROWS / BM, 1), NT, SMEM_P2>>>(
        oh, ol, wot, out, nullptr, nullptr, nullptr, nullptr, bo,
        DIM, DIM, DIM, DIM, 0, 0, 0, 1.0f);
}